// round 14
// baseline (speedup 1.0000x reference)
#include <cuda_runtime.h>
#include <cuda_bf16.h>
#include <cuda_fp16.h>
#include <math.h>

#define NB 64
#define NS 256
#define NV 32000
#define NE 512
#define NH 512
#define NA 512
#define EPSV 1e-5f

// ---------------- scratch (__device__ globals; no allocations allowed) ----------------
__device__ float g_embedded[NB * NE];
__device__ float g_dec_proj[NB * NA];
__device__ float g_scores[NB * NS];
__device__ float g_context[NB * 2 * NH];
__device__ float g_gates_part[4][NB * 2048];
__device__ float g_hl0[NB * NH];
__device__ float g_hl1[NB * NH];
__device__ float g_projctx[NB * NH];
__device__ float g_fused[NB * NH];
__device__ float g_comb[(size_t)NB * NS * NA];       // 16384 x 512 enc_proj scratch
__device__ __half g_encH[(size_t)NB * NS * 1024];    // enc fp16
__device__ __half g_WeH[NA * 1024];                  // W_enc fp16

// ---------------- helpers ----------------
__device__ __forceinline__ float blk_sum(float v, float* red) {
    int t = threadIdx.x, lane = t & 31, w = t >> 5, nw = blockDim.x >> 5;
#pragma unroll
    for (int o = 16; o; o >>= 1) v += __shfl_xor_sync(0xffffffffu, v, o);
    if (lane == 0) red[w] = v;
    __syncthreads();
    if (w == 0) {
        float x = (lane < nw) ? red[lane] : 0.f;
#pragma unroll
        for (int o = 16; o; o >>= 1) x += __shfl_xor_sync(0xffffffffu, x, o);
        if (lane == 0) red[0] = x;
    }
    __syncthreads();
    float r = red[0];
    __syncthreads();
    return r;
}

__device__ __forceinline__ float blk_max(float v, float* red) {
    int t = threadIdx.x, lane = t & 31, w = t >> 5, nw = blockDim.x >> 5;
#pragma unroll
    for (int o = 16; o; o >>= 1) v = fmaxf(v, __shfl_xor_sync(0xffffffffu, v, o));
    if (lane == 0) red[w] = v;
    __syncthreads();
    if (w == 0) {
        float x = (lane < nw) ? red[lane] : -INFINITY;
#pragma unroll
        for (int o = 16; o; o >>= 1) x = fmaxf(x, __shfl_xor_sync(0xffffffffu, x, o));
        if (lane == 0) red[0] = x;
    }
    __syncthreads();
    float r = red[0];
    __syncthreads();
    return r;
}

__device__ __forceinline__ float sigm(float x) { return 1.f / (1.f + expf(-x)); }

__device__ __forceinline__ void mma_fp16(float* d, const unsigned* a, const unsigned* b) {
    asm volatile(
        "mma.sync.aligned.m16n8k16.row.col.f32.f16.f16.f32 "
        "{%0,%1,%2,%3},{%4,%5,%6,%7},{%8,%9},{%0,%1,%2,%3};\n"
        : "+f"(d[0]), "+f"(d[1]), "+f"(d[2]), "+f"(d[3])
        : "r"(a[0]), "r"(a[1]), "r"(a[2]), "r"(a[3]), "r"(b[0]), "r"(b[1]));
}

__device__ __forceinline__ void ldsm4(unsigned* r, unsigned addr) {
    asm volatile("ldmatrix.sync.aligned.m8n8.x4.shared.b16 {%0,%1,%2,%3}, [%4];"
                 : "=r"(r[0]), "=r"(r[1]), "=r"(r[2]), "=r"(r[3]) : "r"(addr));
}

__device__ __forceinline__ void cpasync16(unsigned dst, const void* src) {
    asm volatile("cp.async.cg.shared.global [%0], [%1], 16;" :: "r"(dst), "l"(src));
}

// ---------------- K0: fp32 -> fp16 convert (range of float4s) ----------------
template <int DST>   // 0: enc -> g_encH ; 1: W_enc -> g_WeH
__global__ void k_tohalf(const float* __restrict__ src, int base4, int n4) {
    int i = blockIdx.x * 256 + threadIdx.x;
    if (i >= n4) return;
    i += base4;
    float4 v = ((const float4*)src)[i];
    __half2* hp = (DST == 0) ? (__half2*)g_encH : (__half2*)g_WeH;
    __half2 H0; H0.x = __float2half(v.x); H0.y = __float2half(v.y);
    __half2 H1; H1.x = __float2half(v.z); H1.y = __float2half(v.w);
    hp[i * 2] = H0; hp[i * 2 + 1] = H1;
}

// ---------------- K1: embedding gather + LayerNorm ----------------
__global__ void k_embed_ln(const int* __restrict__ tok, const float* __restrict__ emb,
                           const float* __restrict__ lg, const float* __restrict__ lb) {
    __shared__ float red[32];
    int b = blockIdx.x, t = threadIdx.x;
    int token = tok[b];
    float x = emb[(size_t)token * NE + t];
    float mean = blk_sum(x, red) * (1.f / NE);
    float d = x - mean;
    float var = blk_sum(d * d, red) * (1.f / NE);
    float rstd = rsqrtf(var + EPSV);
    g_embedded[b * NE + t] = d * rstd * lg[t] + lb[t];
}

// ---------------- K2: dec_proj, 8-thread split-K. grid (64,16), block 256 ----------------
__global__ void k_dec_proj(const float* __restrict__ h0, const float* __restrict__ Wd,
                           const float* __restrict__ bd) {
    __shared__ float hs[NH];
    int b = blockIdx.x, t = threadIdx.x;
    int gid = t >> 3, sub = t & 7;
    int c = blockIdx.y * 32 + gid;
    hs[t] = h0[(size_t)(NB + b) * NH + t];
    hs[t + 256] = h0[(size_t)(NB + b) * NH + t + 256];
    __syncthreads();
    const float4* w4 = (const float4*)(Wd + (size_t)c * NH);
    const float4* h4 = (const float4*)hs;
    float acc = 0.f;
#pragma unroll
    for (int i = 0; i < 16; i++) {
        int k = sub + i * 8;
        float4 w = w4[k], h = h4[k];
        acc += w.x * h.x + w.y * h.y + w.z * h.z + w.w * h.w;
    }
#pragma unroll
    for (int o = 4; o; o >>= 1) acc += __shfl_xor_sync(0xffffffffu, acc, o);
    if (sub == 0) g_dec_proj[b * NA + c] = acc + bd[c];
}

// ---------------- K3a: enc_proj GEMM, single fp16 x fp16 -----------------
// C[16384,512] = enc[16384,1024] @ W_enc^T.  Block tile 128x128, KC=32, 256 thr (2x4 warps).
__global__ void __launch_bounds__(256) k_attn_mma2() {
    extern __shared__ __half sm[];
    unsigned sbase = (unsigned)__cvta_generic_to_shared(sm);
    int t = threadIdx.x;
    int row0 = blockIdx.y * 128, col0 = blockIdx.x * 128;
    int wid = t >> 5, lane = t & 31;
    int wm = wid >> 2, wn = wid & 3;          // 2x4 warp grid, warp tile 64x32
    int g = lane >> 2, tig = lane & 3;
    int lrow = lane & 15, lcol = lane >> 4;

    float acc[4][4][4] = {};

    auto stage = [&](int buf, int k0) {
#pragma unroll
        for (int i = 0; i < 2; i++) {
            int c = t + i * 256;
            int r = c >> 2, c8 = (c & 3) * 8;
            size_t gA = (size_t)(row0 + r) * 1024 + k0 + c8;
            size_t gB = (size_t)(col0 + r) * 1024 + k0 + c8;
            unsigned d = sbase + 2u * (buf * 10240 + r * 40 + c8);
            cpasync16(d,            g_encH + gA);
            cpasync16(d + 2 * 5120, g_WeH + gB);
        }
        asm volatile("cp.async.commit_group;" ::: "memory");
    };

    stage(0, 0);
    int buf = 0;
    for (int ki = 0; ki < 32; ki++) {
        if (ki < 31) {
            stage(buf ^ 1, (ki + 1) * 32);
            asm volatile("cp.async.wait_group 1;" ::: "memory");
        } else {
            asm volatile("cp.async.wait_group 0;" ::: "memory");
        }
        __syncthreads();
        int base = buf * 10240;
#pragma unroll
        for (int kk = 0; kk < 32; kk += 16) {
            unsigned ah[4][4], bh[2][4];
#pragma unroll
            for (int mt = 0; mt < 4; mt++) {
                unsigned ad = sbase + 2u * (base + (wm * 64 + mt * 16 + lrow) * 40 + kk + lcol * 8);
                ldsm4(ah[mt], ad);
            }
#pragma unroll
            for (int p = 0; p < 2; p++) {
                unsigned bd = sbase + 2u * (base + 5120 + (wn * 32 + p * 16 + lrow) * 40 + kk + lcol * 8);
                ldsm4(bh[p], bd);
            }
#pragma unroll
            for (int mt = 0; mt < 4; mt++)
#pragma unroll
                for (int nt = 0; nt < 4; nt++) {
                    int p = nt >> 1, h = nt & 1;
                    unsigned bhf[2] = {bh[p][h], bh[p][h + 2]};
                    mma_fp16(acc[mt][nt], ah[mt], bhf);
                }
        }
        __syncthreads();
        buf ^= 1;
    }
#pragma unroll
    for (int mt = 0; mt < 4; mt++) {
        int r = row0 + wm * 64 + mt * 16 + g;
#pragma unroll
        for (int nt = 0; nt < 4; nt++) {
            int c = col0 + wn * 32 + nt * 8 + tig * 2;
            *(float2*)&g_comb[(size_t)r * NA + c]       = make_float2(acc[mt][nt][0], acc[mt][nt][1]);
            *(float2*)&g_comb[(size_t)(r + 8) * NA + c] = make_float2(acc[mt][nt][2], acc[mt][nt][3]);
        }
    }
}

// ---------------- K3b: epilogue (+smem-cached dec_proj+b_enc), LN, tanh, dot(v) ------------
// block 256 (8 warps, 8 rows all sharing one b). grid 2048.
__global__ void __launch_bounds__(256) k_attn_epi(const float* __restrict__ be,
                                                  const float* __restrict__ va,
                                                  const float* __restrict__ lg,
                                                  const float* __restrict__ lb) {
    __shared__ float s_d[512];
    int t = threadIdx.x;
    int wid = t >> 5, lane = t & 31;
    int row = blockIdx.x * 8 + wid;     // row = b*256 + s
    int b = blockIdx.x >> 5;            // 32 blocks per batch element
    s_d[t] = g_dec_proj[b * NA + t] + be[t];
    s_d[t + 256] = g_dec_proj[b * NA + t + 256] + be[t + 256];
    __syncthreads();
    const float* src = g_comb + (size_t)row * NA;
    float x[16];
#pragma unroll
    for (int i = 0; i < 16; i++) {
        int c = lane + i * 32;
        x[i] = src[c] + s_d[c];
    }
    float s = 0.f;
#pragma unroll
    for (int i = 0; i < 16; i++) s += x[i];
#pragma unroll
    for (int o = 16; o; o >>= 1) s += __shfl_xor_sync(0xffffffffu, s, o);
    float mean = s * (1.f / 512.f);
    float vs = 0.f;
#pragma unroll
    for (int i = 0; i < 16; i++) { float d = x[i] - mean; vs += d * d; }
#pragma unroll
    for (int o = 16; o; o >>= 1) vs += __shfl_xor_sync(0xffffffffu, vs, o);
    float rstd = rsqrtf(vs * (1.f / 512.f) + EPSV);
    float sc = 0.f;
#pragma unroll
    for (int i = 0; i < 16; i++) {
        int c = lane + i * 32;
        sc += tanhf((x[i] - mean) * rstd * lg[c] + lb[c]) * va[c];
    }
#pragma unroll
    for (int o = 16; o; o >>= 1) sc += __shfl_xor_sync(0xffffffffu, sc, o);
    if (lane == 0) g_scores[row] = sc;
}

// ---------------- K4: softmax over S ----------------
__global__ void k_softmax(const int* __restrict__ mask, float* __restrict__ out_attn) {
    __shared__ float red[32];
    int b = blockIdx.x, t = threadIdx.x;
    float sc = g_scores[b * NS + t];
    if (mask[b * NS + t] == 0) sc = -INFINITY;
    float mx = blk_max(sc, red);
    float e = expf(sc - mx);
    float sum = blk_sum(e, red);
    float wv = e / sum;
    g_scores[b * NS + t] = wv;
    out_attn[b * NS + t] = wv;
}

// ---------------- K5: context from fp16 enc, split-S. grid (64,8), block 256 --------------
__global__ void k_context() {
    __shared__ float4 part[256];
    int b = blockIdx.x, q = blockIdx.y, t = threadIdx.x;
    int cc = t & 31, sg = t >> 5;
    int f4 = q * 32 + cc;                // which group of 4 values (0..255)
    const __half2* ep = (const __half2*)(g_encH + (size_t)b * NS * 1024);
    float4 acc = make_float4(0.f, 0.f, 0.f, 0.f);
#pragma unroll 4
    for (int s = sg; s < NS; s += 8) {
        float wv = g_scores[b * NS + s];
        __half2 e0 = ep[s * 512 + f4 * 2];
        __half2 e1 = ep[s * 512 + f4 * 2 + 1];
        float2 a0 = __half22float2(e0), a1 = __half22float2(e1);
        acc.x += wv * a0.x; acc.y += wv * a0.y; acc.z += wv * a1.x; acc.w += wv * a1.y;
    }
    part[t] = acc;
    __syncthreads();
    if (t < 32) {
        float4 r = part[t];
#pragma unroll
        for (int g2 = 1; g2 < 8; g2++) {
            float4 p = part[g2 * 32 + t];
            r.x += p.x; r.y += p.y; r.z += p.z; r.w += p.w;
        }
        *(float4*)&g_context[b * 1024 + (q * 32 + t) * 4] = r;
    }
}

// ---------------- K6: LSTM gate GEMM (inline concat), split-K x4. grid (128,4) -------------
// UID 0: U = [embedded | context | h0[0]]  (K=2048)
// UID 1: U = [h_l0 | h0[1]]                (K=1024)
template <int K, int UID>
__device__ __forceinline__ float4 load_u(int b, int k, const float* __restrict__ h0) {
    if (UID == 0) {
        if (k < 512)       return *(const float4*)(g_embedded + b * 512 + k);
        else if (k < 1536) return *(const float4*)(g_context + b * 1024 + (k - 512));
        else               return *(const float4*)(h0 + (size_t)b * 512 + (k - 1536));
    } else {
        if (k < 512)       return *(const float4*)(g_hl0 + b * 512 + k);
        else               return *(const float4*)(h0 + (size_t)(NB + b) * 512 + (k - 512));
    }
}

template <int K, int KX, int UID>
__global__ void __launch_bounds__(256) k_gates(const float* __restrict__ Wih,
                                               const float* __restrict__ Whh,
                                               const float* __restrict__ h0) {
    constexpr int KH = K - KX;
    constexpr int KQ = K / 4;
    __shared__ float Us[64 * 16];
    __shared__ float Wt[16 * 20];
    int t = threadIdx.x;
    int colBase = blockIdx.x * 16;
    int kchunk = blockIdx.y;
    int r = t >> 2;
    int tc = t & 3;
    float acc[4] = {0.f, 0.f, 0.f, 0.f};

    for (int k0 = kchunk * KQ; k0 < (kchunk + 1) * KQ; k0 += 16) {
        __syncthreads();
        {
            float4 v = load_u<K, UID>(r, k0 + tc * 4, h0);
            *(float4*)&Us[r * 16 + tc * 4] = v;
        }
        if (t < 64) {
            int c = r;
            int col = colBase + c;
            const float* src = (k0 < KX) ? (Wih + (size_t)col * KX + k0)
                                         : (Whh + (size_t)col * KH + (k0 - KX));
            float4 v = *(const float4*)(src + tc * 4);
            *(float4*)&Wt[c * 20 + tc * 4] = v;
        }
        __syncthreads();
#pragma unroll
        for (int kq = 0; kq < 4; kq++) {
            float4 x = *(const float4*)&Us[r * 16 + kq * 4];
#pragma unroll
            for (int j = 0; j < 4; j++) {
                int c = tc + 4 * j;
                float4 wv = *(const float4*)&Wt[c * 20 + kq * 4];
                acc[j] += x.x * wv.x + x.y * wv.y + x.z * wv.z + x.w * wv.w;
            }
        }
    }
#pragma unroll
    for (int j = 0; j < 4; j++) {
        int c = colBase + tc + 4 * j;
        g_gates_part[kchunk][(size_t)r * (4 * NH) + c] = acc[j];
    }
}

// ---------------- K7: LSTM cell elementwise (sums 4 gate partials + biases) ----------------
__global__ void k_cell(const float* __restrict__ cprev, float* __restrict__ hOut,
                       float* __restrict__ cOut, const float* __restrict__ bih,
                       const float* __restrict__ bhh, int layer) {
    int b = blockIdx.x, j = threadIdx.x;
    size_t base = (size_t)b * 2048;
    float gi = 0.f, gf = 0.f, gg = 0.f, go = 0.f;
#pragma unroll
    for (int p = 0; p < 4; p++) {
        gi += g_gates_part[p][base + j];
        gf += g_gates_part[p][base + j + 512];
        gg += g_gates_part[p][base + j + 1024];
        go += g_gates_part[p][base + j + 1536];
    }
    gi += bih[j] + bhh[j];
    gf += bih[j + 512] + bhh[j + 512];
    gg += bih[j + 1024] + bhh[j + 1024];
    go += bih[j + 1536] + bhh[j + 1536];
    float ig = sigm(gi);
    float fg = sigm(gf);
    float gt = tanhf(gg);
    float og = sigm(go);
    float c = fg * cprev[(size_t)b * NH + j] + ig * gt;
    float h = og * tanhf(c);
    float* hScr = layer ? g_hl1 : g_hl0;
    hScr[b * NH + j] = h;
    hOut[b * NH + j] = h;
    cOut[b * NH + j] = c;
}

// ---------------- K8: proj_ctx, 8-thread split-K. grid (64,16), block 256 ----------------
__global__ void k_projctx(const float* __restrict__ Wc, const float* __restrict__ bc) {
    __shared__ float cs[2 * NH];
    int b = blockIdx.x, t = threadIdx.x;
    int gid = t >> 3, sub = t & 7;
    int c = blockIdx.y * 32 + gid;
#pragma unroll
    for (int i = 0; i < 4; i++) cs[t + i * 256] = g_context[b * 2 * NH + t + i * 256];
    __syncthreads();
    const float4* w4 = (const float4*)(Wc + (size_t)c * (2 * NH));
    const float4* c4 = (const float4*)cs;
    float acc = 0.f;
#pragma unroll
    for (int i = 0; i < 32; i++) {
        int k = sub + i * 8;
        float4 w = w4[k], h = c4[k];
        acc += w.x * h.x + w.y * h.y + w.z * h.z + w.w * h.w;
    }
#pragma unroll
    for (int o = 4; o; o >>= 1) acc += __shfl_xor_sync(0xffffffffu, acc, o);
    if (sub == 0) g_projctx[b * NH + c] = acc + bc[c];
}

// ---------------- K9: fused = LN(h_l1) + proj_ctx ----------------
__global__ void k_ln_fused(const float* __restrict__ lg, const float* __restrict__ lb) {
    __shared__ float red[32];
    int b = blockIdx.x, t = threadIdx.x;
    float x = g_hl1[b * NH + t];
    float mean = blk_sum(x, red) * (1.f / NH);
    float d = x - mean;
    float var = blk_sum(d * d, red) * (1.f / NH);
    float rstd = rsqrtf(var + EPSV);
    g_fused[b * NH + t] = d * rstd * lg[t] + lb[t] + g_projctx[b * NH + t];
}

// ---------------- K10: logits, single fp16 x fp16 --------------
#define SXS 36
__global__ void __launch_bounds__(256) k_logits_mma(const float* __restrict__ Wo,
                                                    const float* __restrict__ bo,
                                                    float* __restrict__ out) {
    __shared__ __half sAh[64 * SXS];
    __shared__ __half sWh[128 * SXS];
    int t = threadIdx.x;
    int col0 = blockIdx.x * 128;
    int wid = t >> 5, lane = t & 31;
    int wm = wid >> 2, wn = wid & 3;
    int g = lane >> 2, tig = lane & 3;

    float acc[2][4][4] = {};

    for (int k0 = 0; k0 < 512; k0 += 32) {
        __syncthreads();
#pragma unroll
        for (int i = 0; i < 2; i++) {
            int idx = t + i * 256;
            int r = idx >> 3, fc = idx & 7;
            float4 v = *(const float4*)(g_fused + (size_t)r * 512 + k0 + fc * 4);
            int sidx = r * SXS + fc * 4;
            sAh[sidx + 0] = __float2half(v.x);
            sAh[sidx + 1] = __float2half(v.y);
            sAh[sidx + 2] = __float2half(v.z);
            sAh[sidx + 3] = __float2half(v.w);
        }
#pragma unroll
        for (int i = 0; i < 4; i++) {
            int idx = t + i * 256;
            int r = idx >> 3, fc = idx & 7;
            float4 v = *(const float4*)(Wo + (size_t)(col0 + r) * 512 + k0 + fc * 4);
            int sidx = r * SXS + fc * 4;
            sWh[sidx + 0] = __float2half(v.x);
            sWh[sidx + 1] = __float2half(v.y);
            sWh[sidx + 2] = __float2half(v.z);
            sWh[sidx + 3] = __float2half(v.w);
        }
        __syncthreads();
#pragma unroll
        for (int kk = 0; kk < 32; kk += 16) {
            unsigned ah[2][4], bh[4][2];
#pragma unroll
            for (int mt = 0; mt < 2; mt++) {
                int rb = wm * 32 + mt * 16;
                int b0 = (rb + g) * SXS + kk + tig * 2;
                int b1 = (rb + g + 8) * SXS + kk + tig * 2;
                ah[mt][0] = *(const unsigned*)&sAh[b0];
                ah[mt][1] = *(const unsigned*)&sAh[b1];
                ah[mt][2] = *(const unsigned*)&sAh[b0 + 8];
                ah[mt][3] = *(const unsigned*)&sAh[b1 + 8];
            }
#pragma unroll
            for (int nt = 0; nt < 4; nt++) {
                int nb = (wn * 32 + nt * 8 + g) * SXS + kk + tig * 2;
                bh[nt][0] = *(const unsigned*)&sWh[nb];
                bh[nt][1] = *(const unsigned*)&sWh[nb + 8];
            }
#pragma unroll
            for (int mt = 0; mt < 2; mt++)
#pragma unroll
                for (int nt = 0; nt < 4; nt++) {
                    mma_fp16(acc[mt][nt], ah[mt], bh[nt]);
                }
        }
    }
#pragma unroll
    for (int mt = 0; mt < 2; mt++) {
        int r = wm * 32 + mt * 16 + g;
#pragma unroll
        for (int nt = 0; nt < 4; nt++) {
            int c = col0 + wn * 32 + nt * 8 + tig * 2;
            out[(size_t)r * NV + c]           = acc[mt][nt][0] + bo[c];
            out[(size_t)r * NV + c + 1]       = acc[mt][nt][1] + bo[c + 1];
            out[(size_t)(r + 8) * NV + c]     = acc[mt][nt][2] + bo[c];
            out[(size_t)(r + 8) * NV + c + 1] = acc[mt][nt][3] + bo[c + 1];
        }
    }
}

// ---------------- launch ----------------
extern "C" void kernel_launch(void* const* d_in, const int* in_sizes, int n_in,
                              void* d_out, int out_size) {
    const int*   tok   = (const int*)d_in[0];
    const float* h0    = (const float*)d_in[1];
    const float* c0    = (const float*)d_in[2];
    const float* enc   = (const float*)d_in[3];
    const int*   mask  = (const int*)d_in[4];
    const float* emb   = (const float*)d_in[5];
    const float* lng   = (const float*)d_in[6];
    const float* lnb   = (const float*)d_in[7];
    const float* W_enc = (const float*)d_in[8];
    const float* b_enc = (const float*)d_in[9];
    const float* W_dec = (const float*)d_in[10];
    const float* b_dec = (const float*)d_in[11];
    const float* v_att = (const float*)d_in[12];
    const float* lag   = (const float*)d_in[13];
    const float* lab   = (const float*)d_in[14];
    const float* W_ih0 = (const float*)d_in[15];
    const float* W_hh0 = (const float*)d_in[16];
    const float* b_ih0 = (const float*)d_in[17];
    const float* b_hh0 = (const float*)d_in[18];
    const float* W_ih1 = (const float*)d_in[19];
    const float* W_hh1 = (const float*)d_in[20];
    const float* b_ih1 = (const float*)d_in[21];
    const float* b_hh1 = (const float*)d_in[22];
    const float* llg   = (const float*)d_in[23];
    const float* llb   = (const float*)d_in[24];
    const float* W_ctx = (const float*)d_in[25];
    const float* b_ctx = (const float*)d_in[26];
    const float* W_out = (const float*)d_in[27];
    const float* b_out = (const float*)d_in[28];

    float* out = (float*)d_out;
    float* out_logits = out;
    float* out_h = out + (size_t)NB * NV;
    float* out_c = out_h + 2 * NB * NH;
    float* out_attn = out_c + 2 * NB * NH;

    cudaFuncSetAttribute(k_attn_mma2, cudaFuncAttributeMaxDynamicSharedMemorySize, 48 * 1024);

    int encN4 = NB * NS * 1024 / 4;           // 4,194,304 float4s
    int half4 = encN4 / 2;
    // launches 1-5 precede attn so ncu (-s 5 -c 1) samples k_attn_mma2 as launch #6
    k_tohalf<0><<<(half4 + 255) / 256, 256>>>(enc, 0, half4);
    k_tohalf<0><<<(half4 + 255) / 256, 256>>>(enc, half4, half4);
    k_tohalf<1><<<(NA * 1024 / 4 + 255) / 256, 256>>>(W_enc, 0, NA * 1024 / 4);
    k_embed_ln<<<NB, 512>>>(tok, emb, lng, lnb);
    k_dec_proj<<<dim3(NB, 16), 256>>>(h0, W_dec, b_dec);
    k_attn_mma2<<<dim3(4, 128), 256, 40960>>>();
    k_attn_epi<<<2048, 256>>>(b_enc, v_att, lag, lab);
    k_softmax<<<NB, NS>>>(mask, out_attn);
    k_context<<<dim3(NB, 8), 256>>>();
    k_gates<2048, 1536, 0><<<dim3(128, 4), 256>>>(W_ih0, W_hh0, h0);
    k_cell<<<NB, 512>>>(c0, out_h, out_c, b_ih0, b_hh0, 0);
    k_gates<1024, 512, 1><<<dim3(128, 4), 256>>>(W_ih1, W_hh1, h0);
    k_cell<<<NB, 512>>>(c0 + (size_t)NB * NH, out_h + (size_t)NB * NH, out_c + (size_t)NB * NH,
                        b_ih1, b_hh1, 1);
    k_projctx<<<dim3(NB, 16), 256>>>(W_ctx, b_ctx);
    k_ln_fused<<<NB, 512>>>(llg, llb);
    k_logits_mma<<<NV / 128, 256>>>(W_out, b_out, out_logits);
}

// round 15
// speedup vs baseline: 1.3631x; 1.3631x over previous
#include <cuda_runtime.h>
#include <cuda_bf16.h>
#include <cuda_fp16.h>
#include <math.h>

#define NB 64
#define NS 256
#define NV 32000
#define NE 512
#define NH 512
#define NA 512
#define EPSV 1e-5f

// ---------------- scratch (__device__ globals; no allocations allowed) ----------------
__device__ float g_embedded[NB * NE];
__device__ float g_dec_proj[NB * NA];
__device__ float g_scores[NB * NS];
__device__ float g_context[NB * 2 * NH];
__device__ float g_u0[NB * 2048];
__device__ float g_u1[NB * 1024];
__device__ float g_gates_part[4][NB * 2048];
__device__ float g_hl0[NB * NH];
__device__ float g_hl1[NB * NH];
__device__ float g_projctx[NB * NH];
__device__ float g_fused[NB * NH];
__device__ float g_comb[(size_t)NB * NS * NA];       // 16384 x 512 enc_proj scratch
__device__ __half g_encH[(size_t)NB * NS * 1024];    // enc fp16
__device__ __half g_WeH[NA * 1024];                  // W_enc fp16

// ---------------- helpers ----------------
__device__ __forceinline__ float blk_sum(float v, float* red) {
    int t = threadIdx.x, lane = t & 31, w = t >> 5, nw = blockDim.x >> 5;
#pragma unroll
    for (int o = 16; o; o >>= 1) v += __shfl_xor_sync(0xffffffffu, v, o);
    if (lane == 0) red[w] = v;
    __syncthreads();
    if (w == 0) {
        float x = (lane < nw) ? red[lane] : 0.f;
#pragma unroll
        for (int o = 16; o; o >>= 1) x += __shfl_xor_sync(0xffffffffu, x, o);
        if (lane == 0) red[0] = x;
    }
    __syncthreads();
    float r = red[0];
    __syncthreads();
    return r;
}

__device__ __forceinline__ float blk_max(float v, float* red) {
    int t = threadIdx.x, lane = t & 31, w = t >> 5, nw = blockDim.x >> 5;
#pragma unroll
    for (int o = 16; o; o >>= 1) v = fmaxf(v, __shfl_xor_sync(0xffffffffu, v, o));
    if (lane == 0) red[w] = v;
    __syncthreads();
    if (w == 0) {
        float x = (lane < nw) ? red[lane] : -INFINITY;
#pragma unroll
        for (int o = 16; o; o >>= 1) x = fmaxf(x, __shfl_xor_sync(0xffffffffu, x, o));
        if (lane == 0) red[0] = x;
    }
    __syncthreads();
    float r = red[0];
    __syncthreads();
    return r;
}

__device__ __forceinline__ float sigm(float x) { return 1.f / (1.f + expf(-x)); }

__device__ __forceinline__ void mma_fp16(float* d, const unsigned* a, const unsigned* b) {
    asm volatile(
        "mma.sync.aligned.m16n8k16.row.col.f32.f16.f16.f32 "
        "{%0,%1,%2,%3},{%4,%5,%6,%7},{%8,%9},{%0,%1,%2,%3};\n"
        : "+f"(d[0]), "+f"(d[1]), "+f"(d[2]), "+f"(d[3])
        : "r"(a[0]), "r"(a[1]), "r"(a[2]), "r"(a[3]), "r"(b[0]), "r"(b[1]));
}

__device__ __forceinline__ void ldsm4(unsigned* r, unsigned addr) {
    asm volatile("ldmatrix.sync.aligned.m8n8.x4.shared.b16 {%0,%1,%2,%3}, [%4];"
                 : "=r"(r[0]), "=r"(r[1]), "=r"(r[2]), "=r"(r[3]) : "r"(addr));
}

__device__ __forceinline__ void cpasync16(unsigned dst, const void* src) {
    asm volatile("cp.async.cg.shared.global [%0], [%1], 16;" :: "r"(dst), "l"(src));
}

// ---------------- K0: fp32 -> fp16 convert (range of float4s) ----------------
template <int DST>   // 0: enc -> g_encH ; 1: W_enc -> g_WeH
__global__ void k_tohalf(const float* __restrict__ src, int base4, int n4) {
    int i = blockIdx.x * 256 + threadIdx.x;
    if (i >= n4) return;
    i += base4;
    float4 v = ((const float4*)src)[i];
    __half2* hp = (DST == 0) ? (__half2*)g_encH : (__half2*)g_WeH;
    __half2 H0; H0.x = __float2half(v.x); H0.y = __float2half(v.y);
    __half2 H1; H1.x = __float2half(v.z); H1.y = __float2half(v.w);
    hp[i * 2] = H0; hp[i * 2 + 1] = H1;
}

// ---------------- K1: embedding gather + LayerNorm ----------------
__global__ void k_embed_ln(const int* __restrict__ tok, const float* __restrict__ emb,
                           const float* __restrict__ lg, const float* __restrict__ lb) {
    __shared__ float red[32];
    int b = blockIdx.x, t = threadIdx.x;
    int token = tok[b];
    float x = emb[(size_t)token * NE + t];
    float mean = blk_sum(x, red) * (1.f / NE);
    float d = x - mean;
    float var = blk_sum(d * d, red) * (1.f / NE);
    float rstd = rsqrtf(var + EPSV);
    g_embedded[b * NE + t] = d * rstd * lg[t] + lb[t];
}

// ---------------- K2: dec_proj, 8-thread split-K. grid (64,16), block 256 ----------------
__global__ void k_dec_proj(const float* __restrict__ h0, const float* __restrict__ Wd,
                           const float* __restrict__ bd) {
    __shared__ float hs[NH];
    int b = blockIdx.x, t = threadIdx.x;
    int gid = t >> 3, sub = t & 7;
    int c = blockIdx.y * 32 + gid;
    hs[t] = h0[(size_t)(NB + b) * NH + t];
    hs[t + 256] = h0[(size_t)(NB + b) * NH + t + 256];
    __syncthreads();
    const float4* w4 = (const float4*)(Wd + (size_t)c * NH);
    const float4* h4 = (const float4*)hs;
    float acc = 0.f;
#pragma unroll
    for (int i = 0; i < 16; i++) {
        int k = sub + i * 8;
        float4 w = w4[k], h = h4[k];
        acc += w.x * h.x + w.y * h.y + w.z * h.z + w.w * h.w;
    }
#pragma unroll
    for (int o = 4; o; o >>= 1) acc += __shfl_xor_sync(0xffffffffu, acc, o);
    if (sub == 0) g_dec_proj[b * NA + c] = acc + bd[c];
}

// ---------------- K3a: enc_proj GEMM, single fp16 x fp16 -----------------
// C[16384,512] = enc[16384,1024] @ W_enc^T.  Block tile 128x128, KC=32, 256 thr (2x4 warps).
__global__ void __launch_bounds__(256) k_attn_mma2() {
    extern __shared__ __half sm[];
    unsigned sbase = (unsigned)__cvta_generic_to_shared(sm);
    int t = threadIdx.x;
    int row0 = blockIdx.y * 128, col0 = blockIdx.x * 128;
    int wid = t >> 5, lane = t & 31;
    int wm = wid >> 2, wn = wid & 3;          // 2x4 warp grid, warp tile 64x32
    int g = lane >> 2, tig = lane & 3;
    int lrow = lane & 15, lcol = lane >> 4;

    float acc[4][4][4] = {};

    auto stage = [&](int buf, int k0) {
#pragma unroll
        for (int i = 0; i < 2; i++) {
            int c = t + i * 256;
            int r = c >> 2, c8 = (c & 3) * 8;
            size_t gA = (size_t)(row0 + r) * 1024 + k0 + c8;
            size_t gB = (size_t)(col0 + r) * 1024 + k0 + c8;
            unsigned d = sbase + 2u * (buf * 10240 + r * 40 + c8);
            cpasync16(d,            g_encH + gA);
            cpasync16(d + 2 * 5120, g_WeH + gB);
        }
        asm volatile("cp.async.commit_group;" ::: "memory");
    };

    stage(0, 0);
    int buf = 0;
    for (int ki = 0; ki < 32; ki++) {
        if (ki < 31) {
            stage(buf ^ 1, (ki + 1) * 32);
            asm volatile("cp.async.wait_group 1;" ::: "memory");
        } else {
            asm volatile("cp.async.wait_group 0;" ::: "memory");
        }
        __syncthreads();
        int base = buf * 10240;
#pragma unroll
        for (int kk = 0; kk < 32; kk += 16) {
            unsigned ah[4][4], bh[2][4];
#pragma unroll
            for (int mt = 0; mt < 4; mt++) {
                unsigned ad = sbase + 2u * (base + (wm * 64 + mt * 16 + lrow) * 40 + kk + lcol * 8);
                ldsm4(ah[mt], ad);
            }
#pragma unroll
            for (int p = 0; p < 2; p++) {
                unsigned bd = sbase + 2u * (base + 5120 + (wn * 32 + p * 16 + lrow) * 40 + kk + lcol * 8);
                ldsm4(bh[p], bd);
            }
#pragma unroll
            for (int mt = 0; mt < 4; mt++)
#pragma unroll
                for (int nt = 0; nt < 4; nt++) {
                    int p = nt >> 1, h = nt & 1;
                    unsigned bhf[2] = {bh[p][h], bh[p][h + 2]};
                    mma_fp16(acc[mt][nt], ah[mt], bhf);
                }
        }
        __syncthreads();
        buf ^= 1;
    }
#pragma unroll
    for (int mt = 0; mt < 4; mt++) {
        int r = row0 + wm * 64 + mt * 16 + g;
#pragma unroll
        for (int nt = 0; nt < 4; nt++) {
            int c = col0 + wn * 32 + nt * 8 + tig * 2;
            *(float2*)&g_comb[(size_t)r * NA + c]       = make_float2(acc[mt][nt][0], acc[mt][nt][1]);
            *(float2*)&g_comb[(size_t)(r + 8) * NA + c] = make_float2(acc[mt][nt][2], acc[mt][nt][3]);
        }
    }
}

// ---------------- K3b: epilogue (+smem-cached dec_proj+b_enc), LN, tanh, dot(v) ------------
// block 256 (8 warps, 8 rows all sharing one b). grid 2048.
__global__ void __launch_bounds__(256) k_attn_epi(const float* __restrict__ be,
                                                  const float* __restrict__ va,
                                                  const float* __restrict__ lg,
                                                  const float* __restrict__ lb) {
    __shared__ float s_d[512];
    int t = threadIdx.x;
    int wid = t >> 5, lane = t & 31;
    int row = blockIdx.x * 8 + wid;     // row = b*256 + s
    int b = blockIdx.x >> 5;            // 32 blocks per batch element
    s_d[t] = g_dec_proj[b * NA + t] + be[t];
    s_d[t + 256] = g_dec_proj[b * NA + t + 256] + be[t + 256];
    __syncthreads();
    const float* src = g_comb + (size_t)row * NA;
    float x[16];
#pragma unroll
    for (int i = 0; i < 16; i++) {
        int c = lane + i * 32;
        x[i] = src[c] + s_d[c];
    }
    float s = 0.f;
#pragma unroll
    for (int i = 0; i < 16; i++) s += x[i];
#pragma unroll
    for (int o = 16; o; o >>= 1) s += __shfl_xor_sync(0xffffffffu, s, o);
    float mean = s * (1.f / 512.f);
    float vs = 0.f;
#pragma unroll
    for (int i = 0; i < 16; i++) { float d = x[i] - mean; vs += d * d; }
#pragma unroll
    for (int o = 16; o; o >>= 1) vs += __shfl_xor_sync(0xffffffffu, vs, o);
    float rstd = rsqrtf(vs * (1.f / 512.f) + EPSV);
    float sc = 0.f;
#pragma unroll
    for (int i = 0; i < 16; i++) {
        int c = lane + i * 32;
        sc += tanhf((x[i] - mean) * rstd * lg[c] + lb[c]) * va[c];
    }
#pragma unroll
    for (int o = 16; o; o >>= 1) sc += __shfl_xor_sync(0xffffffffu, sc, o);
    if (lane == 0) g_scores[row] = sc;
}

// ---------------- K4: softmax over S ----------------
__global__ void k_softmax(const int* __restrict__ mask, float* __restrict__ out_attn) {
    __shared__ float red[32];
    int b = blockIdx.x, t = threadIdx.x;
    float sc = g_scores[b * NS + t];
    if (mask[b * NS + t] == 0) sc = -INFINITY;
    float mx = blk_max(sc, red);
    float e = expf(sc - mx);
    float sum = blk_sum(e, red);
    float wv = e / sum;
    g_scores[b * NS + t] = wv;
    out_attn[b * NS + t] = wv;
}

// ---------------- K5: context, split-S. grid (64,8), block 256 ----------------
__global__ void k_context(const float* __restrict__ enc) {
    __shared__ float4 part[256];
    int b = blockIdx.x, q = blockIdx.y, t = threadIdx.x;
    int cc = t & 31, sg = t >> 5;
    int f4 = q * 32 + cc;
    const float4* ep = (const float4*)(enc + (size_t)b * NS * 1024);
    float4 acc = make_float4(0.f, 0.f, 0.f, 0.f);
#pragma unroll 4
    for (int s = sg; s < NS; s += 8) {
        float wv = g_scores[b * NS + s];
        float4 e = ep[s * 256 + f4];
        acc.x += wv * e.x; acc.y += wv * e.y; acc.z += wv * e.z; acc.w += wv * e.w;
    }
    part[t] = acc;
    __syncthreads();
    if (t < 32) {
        float4 r = part[t];
#pragma unroll
        for (int g2 = 1; g2 < 8; g2++) {
            float4 p = part[g2 * 32 + t];
            r.x += p.x; r.y += p.y; r.z += p.z; r.w += p.w;
        }
        *(float4*)&g_context[b * 1024 + (q * 32 + t) * 4] = r;
    }
}

// ---------------- concat builders ----------------
__global__ void k_concat0(const float* __restrict__ h0) {
    int b = blockIdx.x;
    for (int k = threadIdx.x; k < 2048; k += blockDim.x) {
        float v;
        if (k < 512) v = g_embedded[b * NE + k];
        else if (k < 1536) v = g_context[b * 1024 + (k - 512)];
        else v = h0[(size_t)b * NH + (k - 1536)];
        g_u0[b * 2048 + k] = v;
    }
}
__global__ void k_concat1(const float* __restrict__ h0) {
    int b = blockIdx.x;
    for (int k = threadIdx.x; k < 1024; k += blockDim.x) {
        float v = (k < 512) ? g_hl0[b * NH + k] : h0[(size_t)NB * NH + b * NH + (k - 512)];
        g_u1[b * 1024 + k] = v;
    }
}

// ---------------- K6: LSTM gate GEMM, split-K x4 into partials. grid (128,4) -------------
template <int K, int KX, int UID>
__global__ void __launch_bounds__(256) k_gates(const float* __restrict__ Wih,
                                               const float* __restrict__ Whh) {
    constexpr int KH = K - KX;
    constexpr int KQ = K / 4;
    const float* U = (UID == 0) ? g_u0 : g_u1;
    __shared__ float Us[64 * 16];
    __shared__ float Wt[16 * 20];
    int t = threadIdx.x;
    int colBase = blockIdx.x * 16;
    int kchunk = blockIdx.y;
    int r = t >> 2;
    int tc = t & 3;
    float acc[4] = {0.f, 0.f, 0.f, 0.f};

    for (int k0 = kchunk * KQ; k0 < (kchunk + 1) * KQ; k0 += 16) {
        __syncthreads();
        {
            float4 v = *(const float4*)(U + (size_t)r * K + k0 + tc * 4);
            *(float4*)&Us[r * 16 + tc * 4] = v;
        }
        if (t < 64) {
            int c = r;
            int col = colBase + c;
            const float* src = (k0 < KX) ? (Wih + (size_t)col * KX + k0)
                                         : (Whh + (size_t)col * KH + (k0 - KX));
            float4 v = *(const float4*)(src + tc * 4);
            *(float4*)&Wt[c * 20 + tc * 4] = v;
        }
        __syncthreads();
#pragma unroll
        for (int kq = 0; kq < 4; kq++) {
            float4 x = *(const float4*)&Us[r * 16 + kq * 4];
#pragma unroll
            for (int j = 0; j < 4; j++) {
                int c = tc + 4 * j;
                float4 wv = *(const float4*)&Wt[c * 20 + kq * 4];
                acc[j] += x.x * wv.x + x.y * wv.y + x.z * wv.z + x.w * wv.w;
            }
        }
    }
#pragma unroll
    for (int j = 0; j < 4; j++) {
        int c = colBase + tc + 4 * j;
        g_gates_part[kchunk][(size_t)r * (4 * NH) + c] = acc[j];
    }
}

// ---------------- K7: LSTM cell elementwise (sums 4 gate partials + biases) ----------------
__global__ void k_cell(const float* __restrict__ cprev, float* __restrict__ hOut,
                       float* __restrict__ cOut, const float* __restrict__ bih,
                       const float* __restrict__ bhh, int layer) {
    int b = blockIdx.x, j = threadIdx.x;
    size_t base = (size_t)b * 2048;
    float gi = 0.f, gf = 0.f, gg = 0.f, go = 0.f;
#pragma unroll
    for (int p = 0; p < 4; p++) {
        gi += g_gates_part[p][base + j];
        gf += g_gates_part[p][base + j + 512];
        gg += g_gates_part[p][base + j + 1024];
        go += g_gates_part[p][base + j + 1536];
    }
    gi += bih[j] + bhh[j];
    gf += bih[j + 512] + bhh[j + 512];
    gg += bih[j + 1024] + bhh[j + 1024];
    go += bih[j + 1536] + bhh[j + 1536];
    float ig = sigm(gi);
    float fg = sigm(gf);
    float gt = tanhf(gg);
    float og = sigm(go);
    float c = fg * cprev[(size_t)b * NH + j] + ig * gt;
    float h = og * tanhf(c);
    float* hScr = layer ? g_hl1 : g_hl0;
    hScr[b * NH + j] = h;
    hOut[b * NH + j] = h;
    cOut[b * NH + j] = c;
}

// ---------------- K8: proj_ctx, 8-thread split-K. grid (64,16), block 256 ----------------
__global__ void k_projctx(const float* __restrict__ Wc, const float* __restrict__ bc) {
    __shared__ float cs[2 * NH];
    int b = blockIdx.x, t = threadIdx.x;
    int gid = t >> 3, sub = t & 7;
    int c = blockIdx.y * 32 + gid;
#pragma unroll
    for (int i = 0; i < 4; i++) cs[t + i * 256] = g_context[b * 2 * NH + t + i * 256];
    __syncthreads();
    const float4* w4 = (const float4*)(Wc + (size_t)c * (2 * NH));
    const float4* c4 = (const float4*)cs;
    float acc = 0.f;
#pragma unroll
    for (int i = 0; i < 32; i++) {
        int k = sub + i * 8;
        float4 w = w4[k], h = c4[k];
        acc += w.x * h.x + w.y * h.y + w.z * h.z + w.w * h.w;
    }
#pragma unroll
    for (int o = 4; o; o >>= 1) acc += __shfl_xor_sync(0xffffffffu, acc, o);
    if (sub == 0) g_projctx[b * NH + c] = acc + bc[c];
}

// ---------------- K9: fused = LN(h_l1) + proj_ctx ----------------
__global__ void k_ln_fused(const float* __restrict__ lg, const float* __restrict__ lb) {
    __shared__ float red[32];
    int b = blockIdx.x, t = threadIdx.x;
    float x = g_hl1[b * NH + t];
    float mean = blk_sum(x, red) * (1.f / NH);
    float d = x - mean;
    float var = blk_sum(d * d, red) * (1.f / NH);
    float rstd = rsqrtf(var + EPSV);
    g_fused[b * NH + t] = d * rstd * lg[t] + lb[t] + g_projctx[b * NH + t];
}

// ---------------- K10: logits, single fp16 x fp16 --------------
#define SXS 36
__global__ void __launch_bounds__(256) k_logits_mma(const float* __restrict__ Wo,
                                                    const float* __restrict__ bo,
                                                    float* __restrict__ out) {
    __shared__ __half sAh[64 * SXS];
    __shared__ __half sWh[128 * SXS];
    int t = threadIdx.x;
    int col0 = blockIdx.x * 128;
    int wid = t >> 5, lane = t & 31;
    int wm = wid >> 2, wn = wid & 3;
    int g = lane >> 2, tig = lane & 3;

    float acc[2][4][4] = {};

    for (int k0 = 0; k0 < 512; k0 += 32) {
        __syncthreads();
#pragma unroll
        for (int i = 0; i < 2; i++) {
            int idx = t + i * 256;
            int r = idx >> 3, fc = idx & 7;
            float4 v = *(const float4*)(g_fused + (size_t)r * 512 + k0 + fc * 4);
            int sidx = r * SXS + fc * 4;
            sAh[sidx + 0] = __float2half(v.x);
            sAh[sidx + 1] = __float2half(v.y);
            sAh[sidx + 2] = __float2half(v.z);
            sAh[sidx + 3] = __float2half(v.w);
        }
#pragma unroll
        for (int i = 0; i < 4; i++) {
            int idx = t + i * 256;
            int r = idx >> 3, fc = idx & 7;
            float4 v = *(const float4*)(Wo + (size_t)(col0 + r) * 512 + k0 + fc * 4);
            int sidx = r * SXS + fc * 4;
            sWh[sidx + 0] = __float2half(v.x);
            sWh[sidx + 1] = __float2half(v.y);
            sWh[sidx + 2] = __float2half(v.z);
            sWh[sidx + 3] = __float2half(v.w);
        }
        __syncthreads();
#pragma unroll
        for (int kk = 0; kk < 32; kk += 16) {
            unsigned ah[2][4], bh[4][2];
#pragma unroll
            for (int mt = 0; mt < 2; mt++) {
                int rb = wm * 32 + mt * 16;
                int b0 = (rb + g) * SXS + kk + tig * 2;
                int b1 = (rb + g + 8) * SXS + kk + tig * 2;
                ah[mt][0] = *(const unsigned*)&sAh[b0];
                ah[mt][1] = *(const unsigned*)&sAh[b1];
                ah[mt][2] = *(const unsigned*)&sAh[b0 + 8];
                ah[mt][3] = *(const unsigned*)&sAh[b1 + 8];
            }
#pragma unroll
            for (int nt = 0; nt < 4; nt++) {
                int nb = (wn * 32 + nt * 8 + g) * SXS + kk + tig * 2;
                bh[nt][0] = *(const unsigned*)&sWh[nb];
                bh[nt][1] = *(const unsigned*)&sWh[nb + 8];
            }
#pragma unroll
            for (int mt = 0; mt < 2; mt++)
#pragma unroll
                for (int nt = 0; nt < 4; nt++) {
                    mma_fp16(acc[mt][nt], ah[mt], bh[nt]);
                }
        }
    }
#pragma unroll
    for (int mt = 0; mt < 2; mt++) {
        int r = wm * 32 + mt * 16 + g;
#pragma unroll
        for (int nt = 0; nt < 4; nt++) {
            int c = col0 + wn * 32 + nt * 8 + tig * 2;
            out[(size_t)r * NV + c]           = acc[mt][nt][0] + bo[c];
            out[(size_t)r * NV + c + 1]       = acc[mt][nt][1] + bo[c + 1];
            out[(size_t)(r + 8) * NV + c]     = acc[mt][nt][2] + bo[c];
            out[(size_t)(r + 8) * NV + c + 1] = acc[mt][nt][3] + bo[c + 1];
        }
    }
}

// ---------------- launch ----------------
extern "C" void kernel_launch(void* const* d_in, const int* in_sizes, int n_in,
                              void* d_out, int out_size) {
    const int*   tok   = (const int*)d_in[0];
    const float* h0    = (const float*)d_in[1];
    const float* c0    = (const float*)d_in[2];
    const float* enc   = (const float*)d_in[3];
    const int*   mask  = (const int*)d_in[4];
    const float* emb   = (const float*)d_in[5];
    const float* lng   = (const float*)d_in[6];
    const float* lnb   = (const float*)d_in[7];
    const float* W_enc = (const float*)d_in[8];
    const float* b_enc = (const float*)d_in[9];
    const float* W_dec = (const float*)d_in[10];
    const float* b_dec = (const float*)d_in[11];
    const float* v_att = (const float*)d_in[12];
    const float* lag   = (const float*)d_in[13];
    const float* lab   = (const float*)d_in[14];
    const float* W_ih0 = (const float*)d_in[15];
    const float* W_hh0 = (const float*)d_in[16];
    const float* b_ih0 = (const float*)d_in[17];
    const float* b_hh0 = (const float*)d_in[18];
    const float* W_ih1 = (const float*)d_in[19];
    const float* W_hh1 = (const float*)d_in[20];
    const float* b_ih1 = (const float*)d_in[21];
    const float* b_hh1 = (const float*)d_in[22];
    const float* llg   = (const float*)d_in[23];
    const float* llb   = (const float*)d_in[24];
    const float* W_ctx = (const float*)d_in[25];
    const float* b_ctx = (const float*)d_in[26];
    const float* W_out = (const float*)d_in[27];
    const float* b_out = (const float*)d_in[28];

    float* out = (float*)d_out;
    float* out_logits = out;
    float* out_h = out + (size_t)NB * NV;
    float* out_c = out_h + 2 * NB * NH;
    float* out_attn = out_c + 2 * NB * NH;

    cudaFuncSetAttribute(k_attn_mma2, cudaFuncAttributeMaxDynamicSharedMemorySize, 48 * 1024);

    int encN4 = NB * NS * 1024 / 4;           // 4,194,304 float4s
    int half4 = encN4 / 2;
    // launches 1-5 precede attn so ncu (-s 5 -c 1) samples k_attn_mma2 as launch #6
    k_tohalf<0><<<(half4 + 255) / 256, 256>>>(enc, 0, half4);
    k_tohalf<0><<<(half4 + 255) / 256, 256>>>(enc, half4, half4);
    k_tohalf<1><<<(NA * 1024 / 4 + 255) / 256, 256>>>(W_enc, 0, NA * 1024 / 4);
    k_embed_ln<<<NB, 512>>>(tok, emb, lng, lnb);
    k_dec_proj<<<dim3(NB, 16), 256>>>(h0, W_dec, b_dec);
    k_attn_mma2<<<dim3(4, 128), 256, 40960>>>();
    k_attn_epi<<<2048, 256>>>(b_enc, v_att, lag, lab);
    k_softmax<<<NB, NS>>>(mask, out_attn);
    k_context<<<dim3(NB, 8), 256>>>(enc);
    k_concat0<<<NB, 256>>>(h0);
    k_gates<2048, 1536, 0><<<dim3(128, 4), 256>>>(W_ih0, W_hh0);
    k_cell<<<NB, 512>>>(c0, out_h, out_c, b_ih0, b_hh0, 0);
    k_concat1<<<NB, 256>>>(h0);
    k_gates<1024, 512, 1><<<dim3(128, 4), 256>>>(W_ih1, W_hh1);
    k_cell<<<NB, 512>>>(c0 + (size_t)NB * NH, out_h + (size_t)NB * NH, out_c + (size_t)NB * NH,
                        b_ih1, b_hh1, 1);
    k_projctx<<<dim3(NB, 16), 256>>>(W_ctx, b_ctx);
    k_ln_fused<<<NB, 512>>>(llg, llb);
    k_logits_mma<<<NV / 128, 256>>>(W_out, b_out, out_logits);
}

// round 16
// speedup vs baseline: 1.4401x; 1.0564x over previous
#include <cuda_runtime.h>
#include <cuda_bf16.h>
#include <cuda_fp16.h>
#include <math.h>

#define NB 64
#define NS 256
#define NV 32000
#define NE 512
#define NH 512
#define NA 512
#define EPSV 1e-5f

// ---------------- scratch (__device__ globals; no allocations allowed) ----------------
__device__ float g_dec_proj[NB * NA];
__device__ float g_scores[NB * NS];
__device__ float g_u0[NB * 2048];                    // [emb(512) | ctx(1024) | h0[0](512)]
__device__ float g_u1[NB * 1024];                    // [h_l0(512) | h0[1](512)]
__device__ float g_gates_part[4][NB * 2048];
__device__ float g_projctx[NB * NH];
__device__ float g_fused[NB * NH];
__device__ __half g_combH[(size_t)NB * NS * NA];     // 16384 x 512 enc_proj scratch (fp16)
__device__ __half g_encH[(size_t)NB * NS * 1024];    // enc fp16
__device__ __half g_WeH[NA * 1024];                  // W_enc fp16

// ---------------- helpers ----------------
__device__ __forceinline__ float blk_sum(float v, float* red) {
    int t = threadIdx.x, lane = t & 31, w = t >> 5, nw = blockDim.x >> 5;
#pragma unroll
    for (int o = 16; o; o >>= 1) v += __shfl_xor_sync(0xffffffffu, v, o);
    if (lane == 0) red[w] = v;
    __syncthreads();
    if (w == 0) {
        float x = (lane < nw) ? red[lane] : 0.f;
#pragma unroll
        for (int o = 16; o; o >>= 1) x += __shfl_xor_sync(0xffffffffu, x, o);
        if (lane == 0) red[0] = x;
    }
    __syncthreads();
    float r = red[0];
    __syncthreads();
    return r;
}

__device__ __forceinline__ float blk_max(float v, float* red) {
    int t = threadIdx.x, lane = t & 31, w = t >> 5, nw = blockDim.x >> 5;
#pragma unroll
    for (int o = 16; o; o >>= 1) v = fmaxf(v, __shfl_xor_sync(0xffffffffu, v, o));
    if (lane == 0) red[w] = v;
    __syncthreads();
    if (w == 0) {
        float x = (lane < nw) ? red[lane] : -INFINITY;
#pragma unroll
        for (int o = 16; o; o >>= 1) x = fmaxf(x, __shfl_xor_sync(0xffffffffu, x, o));
        if (lane == 0) red[0] = x;
    }
    __syncthreads();
    float r = red[0];
    __syncthreads();
    return r;
}

__device__ __forceinline__ float sigm(float x) { return 1.f / (1.f + expf(-x)); }

__device__ __forceinline__ void mma_fp16(float* d, const unsigned* a, const unsigned* b) {
    asm volatile(
        "mma.sync.aligned.m16n8k16.row.col.f32.f16.f16.f32 "
        "{%0,%1,%2,%3},{%4,%5,%6,%7},{%8,%9},{%0,%1,%2,%3};\n"
        : "+f"(d[0]), "+f"(d[1]), "+f"(d[2]), "+f"(d[3])
        : "r"(a[0]), "r"(a[1]), "r"(a[2]), "r"(a[3]), "r"(b[0]), "r"(b[1]));
}

__device__ __forceinline__ void ldsm4(unsigned* r, unsigned addr) {
    asm volatile("ldmatrix.sync.aligned.m8n8.x4.shared.b16 {%0,%1,%2,%3}, [%4];"
                 : "=r"(r[0]), "=r"(r[1]), "=r"(r[2]), "=r"(r[3]) : "r"(addr));
}

__device__ __forceinline__ void cpasync16(unsigned dst, const void* src) {
    asm volatile("cp.async.cg.shared.global [%0], [%1], 16;" :: "r"(dst), "l"(src));
}

// ---------------- K0: fp32 -> fp16 convert (range of float4s) ----------------
template <int DST>   // 0: enc -> g_encH ; 1: W_enc -> g_WeH
__global__ void k_tohalf(const float* __restrict__ src, int base4, int n4) {
    int i = blockIdx.x * 256 + threadIdx.x;
    if (i >= n4) return;
    i += base4;
    float4 v = ((const float4*)src)[i];
    __half2* hp = (DST == 0) ? (__half2*)g_encH : (__half2*)g_WeH;
    __half2 H0; H0.x = __float2half(v.x); H0.y = __float2half(v.y);
    __half2 H1; H1.x = __float2half(v.z); H1.y = __float2half(v.w);
    hp[i * 2] = H0; hp[i * 2 + 1] = H1;
}

// ---------------- K1: embedding gather + LayerNorm -> g_u0[:, 0:512] ----------------
__global__ void k_embed_ln(const int* __restrict__ tok, const float* __restrict__ emb,
                           const float* __restrict__ lg, const float* __restrict__ lb) {
    __shared__ float red[32];
    int b = blockIdx.x, t = threadIdx.x;
    int token = tok[b];
    float x = emb[(size_t)token * NE + t];
    float mean = blk_sum(x, red) * (1.f / NE);
    float d = x - mean;
    float var = blk_sum(d * d, red) * (1.f / NE);
    float rstd = rsqrtf(var + EPSV);
    g_u0[b * 2048 + t] = d * rstd * lg[t] + lb[t];
}

// ---------------- K1b: copy static h0 slices into u0/u1 ----------------
__global__ void k_copy_h0(const float* __restrict__ h0) {
    int b = blockIdx.x, t = threadIdx.x;
    g_u0[b * 2048 + 1536 + t] = h0[(size_t)b * NH + t];          // h0[0]
    g_u1[b * 1024 + 512 + t] = h0[(size_t)(NB + b) * NH + t];    // h0[1]
}

// ---------------- K2: dec_proj, 8-thread split-K. grid (64,16), block 256 ----------------
__global__ void k_dec_proj(const float* __restrict__ h0, const float* __restrict__ Wd,
                           const float* __restrict__ bd) {
    __shared__ float hs[NH];
    int b = blockIdx.x, t = threadIdx.x;
    int gid = t >> 3, sub = t & 7;
    int c = blockIdx.y * 32 + gid;
    hs[t] = h0[(size_t)(NB + b) * NH + t];
    hs[t + 256] = h0[(size_t)(NB + b) * NH + t + 256];
    __syncthreads();
    const float4* w4 = (const float4*)(Wd + (size_t)c * NH);
    const float4* h4 = (const float4*)hs;
    float acc = 0.f;
#pragma unroll
    for (int i = 0; i < 16; i++) {
        int k = sub + i * 8;
        float4 w = w4[k], h = h4[k];
        acc += w.x * h.x + w.y * h.y + w.z * h.z + w.w * h.w;
    }
#pragma unroll
    for (int o = 4; o; o >>= 1) acc += __shfl_xor_sync(0xffffffffu, acc, o);
    if (sub == 0) g_dec_proj[b * NA + c] = acc + bd[c];
}

// ---------------- K3a: enc_proj GEMM, single fp16 x fp16, fp16 output -----------------
// C[16384,512] = enc[16384,1024] @ W_enc^T.  Block tile 128x128, KC=32, 256 thr (2x4 warps).
__global__ void __launch_bounds__(256) k_attn_mma2() {
    extern __shared__ __half sm[];
    unsigned sbase = (unsigned)__cvta_generic_to_shared(sm);
    int t = threadIdx.x;
    int row0 = blockIdx.y * 128, col0 = blockIdx.x * 128;
    int wid = t >> 5, lane = t & 31;
    int wm = wid >> 2, wn = wid & 3;          // 2x4 warp grid, warp tile 64x32
    int g = lane >> 2, tig = lane & 3;
    int lrow = lane & 15, lcol = lane >> 4;

    float acc[4][4][4] = {};

    auto stage = [&](int buf, int k0) {
#pragma unroll
        for (int i = 0; i < 2; i++) {
            int c = t + i * 256;
            int r = c >> 2, c8 = (c & 3) * 8;
            size_t gA = (size_t)(row0 + r) * 1024 + k0 + c8;
            size_t gB = (size_t)(col0 + r) * 1024 + k0 + c8;
            unsigned d = sbase + 2u * (buf * 10240 + r * 40 + c8);
            cpasync16(d,            g_encH + gA);
            cpasync16(d + 2 * 5120, g_WeH + gB);
        }
        asm volatile("cp.async.commit_group;" ::: "memory");
    };

    stage(0, 0);
    int buf = 0;
    for (int ki = 0; ki < 32; ki++) {
        if (ki < 31) {
            stage(buf ^ 1, (ki + 1) * 32);
            asm volatile("cp.async.wait_group 1;" ::: "memory");
        } else {
            asm volatile("cp.async.wait_group 0;" ::: "memory");
        }
        __syncthreads();
        int base = buf * 10240;
#pragma unroll
        for (int kk = 0; kk < 32; kk += 16) {
            unsigned ah[4][4], bh[2][4];
#pragma unroll
            for (int mt = 0; mt < 4; mt++) {
                unsigned ad = sbase + 2u * (base + (wm * 64 + mt * 16 + lrow) * 40 + kk + lcol * 8);
                ldsm4(ah[mt], ad);
            }
#pragma unroll
            for (int p = 0; p < 2; p++) {
                unsigned bd = sbase + 2u * (base + 5120 + (wn * 32 + p * 16 + lrow) * 40 + kk + lcol * 8);
                ldsm4(bh[p], bd);
            }
#pragma unroll
            for (int mt = 0; mt < 4; mt++)
#pragma unroll
                for (int nt = 0; nt < 4; nt++) {
                    int p = nt >> 1, h = nt & 1;
                    unsigned bhf[2] = {bh[p][h], bh[p][h + 2]};
                    mma_fp16(acc[mt][nt], ah[mt], bhf);
                }
        }
        __syncthreads();
        buf ^= 1;
    }
#pragma unroll
    for (int mt = 0; mt < 4; mt++) {
        int r = row0 + wm * 64 + mt * 16 + g;
#pragma unroll
        for (int nt = 0; nt < 4; nt++) {
            int c = col0 + wn * 32 + nt * 8 + tig * 2;
            *(__half2*)&g_combH[(size_t)r * NA + c] =
                __floats2half2_rn(acc[mt][nt][0], acc[mt][nt][1]);
            *(__half2*)&g_combH[(size_t)(r + 8) * NA + c] =
                __floats2half2_rn(acc[mt][nt][2], acc[mt][nt][3]);
        }
    }
}

// ---------------- K3b: epilogue (+smem-cached dec_proj+b_enc), LN, tanh, dot(v) ------------
// block 256 (8 warps, 8 rows all sharing one b). grid 2048.
__global__ void __launch_bounds__(256) k_attn_epi(const float* __restrict__ be,
                                                  const float* __restrict__ va,
                                                  const float* __restrict__ lg,
                                                  const float* __restrict__ lb) {
    __shared__ float s_d[512];
    int t = threadIdx.x;
    int wid = t >> 5, lane = t & 31;
    int row = blockIdx.x * 8 + wid;     // row = b*256 + s
    int b = blockIdx.x >> 5;            // 32 blocks per batch element
    s_d[t] = g_dec_proj[b * NA + t] + be[t];
    s_d[t + 256] = g_dec_proj[b * NA + t + 256] + be[t + 256];
    __syncthreads();
    const __half* src = g_combH + (size_t)row * NA;
    float x[16];
#pragma unroll
    for (int i = 0; i < 16; i++) {
        int c = lane + i * 32;
        x[i] = __half2float(src[c]) + s_d[c];
    }
    float s = 0.f;
#pragma unroll
    for (int i = 0; i < 16; i++) s += x[i];
#pragma unroll
    for (int o = 16; o; o >>= 1) s += __shfl_xor_sync(0xffffffffu, s, o);
    float mean = s * (1.f / 512.f);
    float vs = 0.f;
#pragma unroll
    for (int i = 0; i < 16; i++) { float d = x[i] - mean; vs += d * d; }
#pragma unroll
    for (int o = 16; o; o >>= 1) vs += __shfl_xor_sync(0xffffffffu, vs, o);
    float rstd = rsqrtf(vs * (1.f / 512.f) + EPSV);
    float sc = 0.f;
#pragma unroll
    for (int i = 0; i < 16; i++) {
        int c = lane + i * 32;
        sc += tanhf((x[i] - mean) * rstd * lg[c] + lb[c]) * va[c];
    }
#pragma unroll
    for (int o = 16; o; o >>= 1) sc += __shfl_xor_sync(0xffffffffu, sc, o);
    if (lane == 0) g_scores[row] = sc;
}

// ---------------- K4: fused softmax + context -> g_u0[:, 512:1536]. grid (64,8) ----------
__global__ void __launch_bounds__(256) k_ctx(const int* __restrict__ mask,
                                             const float* __restrict__ enc,
                                             float* __restrict__ out_attn) {
    __shared__ float red[32];
    __shared__ float ws[NS];
    __shared__ float4 part[256];
    int b = blockIdx.x, q = blockIdx.y, t = threadIdx.x;
    // softmax (recomputed per block; 256 values, cheap)
    float sc = g_scores[b * NS + t];
    if (mask[b * NS + t] == 0) sc = -INFINITY;
    float mx = blk_max(sc, red);
    float e = expf(sc - mx);
    float sum = blk_sum(e, red);
    float wv = e / sum;
    ws[t] = wv;
    if (q == 0) out_attn[b * NS + t] = wv;
    __syncthreads();
    // context partial over S
    int cc = t & 31, sg = t >> 5;
    int f4 = q * 32 + cc;
    const float4* ep = (const float4*)(enc + (size_t)b * NS * 1024);
    float4 acc = make_float4(0.f, 0.f, 0.f, 0.f);
#pragma unroll 4
    for (int s = sg; s < NS; s += 8) {
        float w = ws[s];
        float4 ev = ep[s * 256 + f4];
        acc.x += w * ev.x; acc.y += w * ev.y; acc.z += w * ev.z; acc.w += w * ev.w;
    }
    part[t] = acc;
    __syncthreads();
    if (t < 32) {
        float4 r = part[t];
#pragma unroll
        for (int g2 = 1; g2 < 8; g2++) {
            float4 p = part[g2 * 32 + t];
            r.x += p.x; r.y += p.y; r.z += p.z; r.w += p.w;
        }
        *(float4*)&g_u0[b * 2048 + 512 + (q * 32 + t) * 4] = r;
    }
}

// ---------------- K6: LSTM gate GEMM, split-K x4 into partials. grid (128,4) -------------
template <int K, int KX, int UID>
__global__ void __launch_bounds__(256) k_gates(const float* __restrict__ Wih,
                                               const float* __restrict__ Whh) {
    constexpr int KH = K - KX;
    constexpr int KQ = K / 4;
    const float* U = (UID == 0) ? g_u0 : g_u1;
    __shared__ float Us[64 * 16];
    __shared__ float Wt[16 * 20];
    int t = threadIdx.x;
    int colBase = blockIdx.x * 16;
    int kchunk = blockIdx.y;
    int r = t >> 2;
    int tc = t & 3;
    float acc[4] = {0.f, 0.f, 0.f, 0.f};

    for (int k0 = kchunk * KQ; k0 < (kchunk + 1) * KQ; k0 += 16) {
        __syncthreads();
        {
            float4 v = *(const float4*)(U + (size_t)r * K + k0 + tc * 4);
            *(float4*)&Us[r * 16 + tc * 4] = v;
        }
        if (t < 64) {
            int c = r;
            int col = colBase + c;
            const float* src = (k0 < KX) ? (Wih + (size_t)col * KX + k0)
                                         : (Whh + (size_t)col * KH + (k0 - KX));
            float4 v = *(const float4*)(src + tc * 4);
            *(float4*)&Wt[c * 20 + tc * 4] = v;
        }
        __syncthreads();
#pragma unroll
        for (int kq = 0; kq < 4; kq++) {
            float4 x = *(const float4*)&Us[r * 16 + kq * 4];
#pragma unroll
            for (int j = 0; j < 4; j++) {
                int c = tc + 4 * j;
                float4 wv = *(const float4*)&Wt[c * 20 + kq * 4];
                acc[j] += x.x * wv.x + x.y * wv.y + x.z * wv.z + x.w * wv.w;
            }
        }
    }
#pragma unroll
    for (int j = 0; j < 4; j++) {
        int c = colBase + tc + 4 * j;
        g_gates_part[kchunk][(size_t)r * (4 * NH) + c] = acc[j];
    }
}

// ---------------- gate partial summation helper ----------------
__device__ __forceinline__ void gate_sums(int b, int j, const float* bih, const float* bhh,
                                          float& gi, float& gf, float& gg, float& go) {
    size_t base = (size_t)b * 2048;
    gi = gf = gg = go = 0.f;
#pragma unroll
    for (int p = 0; p < 4; p++) {
        gi += g_gates_part[p][base + j];
        gf += g_gates_part[p][base + j + 512];
        gg += g_gates_part[p][base + j + 1024];
        go += g_gates_part[p][base + j + 1536];
    }
    gi += bih[j] + bhh[j];
    gf += bih[j + 512] + bhh[j + 512];
    gg += bih[j + 1024] + bhh[j + 1024];
    go += bih[j + 1536] + bhh[j + 1536];
}

// ---------------- K7a: LSTM cell layer 0 (h -> g_u1 lower half) ----------------
__global__ void k_cell0(const float* __restrict__ cprev, float* __restrict__ hOut,
                        float* __restrict__ cOut, const float* __restrict__ bih,
                        const float* __restrict__ bhh) {
    int b = blockIdx.x, j = threadIdx.x;
    float gi, gf, gg, go;
    gate_sums(b, j, bih, bhh, gi, gf, gg, go);
    float ig = sigm(gi), fg = sigm(gf), gt = tanhf(gg), og = sigm(go);
    float c = fg * cprev[(size_t)b * NH + j] + ig * gt;
    float h = og * tanhf(c);
    g_u1[b * 1024 + j] = h;
    hOut[b * NH + j] = h;
    cOut[b * NH + j] = c;
}

// ---------------- K7b: LSTM cell layer 1 + fused LN + projctx -> g_fused ----------------
__global__ void k_cell1(const float* __restrict__ cprev, float* __restrict__ hOut,
                        float* __restrict__ cOut, const float* __restrict__ bih,
                        const float* __restrict__ bhh, const float* __restrict__ lg,
                        const float* __restrict__ lb) {
    __shared__ float red[32];
    int b = blockIdx.x, j = threadIdx.x;
    float gi, gf, gg, go;
    gate_sums(b, j, bih, bhh, gi, gf, gg, go);
    float ig = sigm(gi), fg = sigm(gf), gt = tanhf(gg), og = sigm(go);
    float c = fg * cprev[(size_t)b * NH + j] + ig * gt;
    float h = og * tanhf(c);
    hOut[b * NH + j] = h;
    cOut[b * NH + j] = c;
    float mean = blk_sum(h, red) * (1.f / NH);
    float d = h - mean;
    float var = blk_sum(d * d, red) * (1.f / NH);
    float rstd = rsqrtf(var + EPSV);
    g_fused[b * NH + j] = d * rstd * lg[j] + lb[j] + g_projctx[b * NH + j];
}

// ---------------- K8: proj_ctx (ctx from g_u0), 8-thread split-K. grid (64,16) ------------
__global__ void k_projctx(const float* __restrict__ Wc, const float* __restrict__ bc) {
    __shared__ float cs[2 * NH];
    int b = blockIdx.x, t = threadIdx.x;
    int gid = t >> 3, sub = t & 7;
    int c = blockIdx.y * 32 + gid;
#pragma unroll
    for (int i = 0; i < 4; i++) cs[t + i * 256] = g_u0[b * 2048 + 512 + t + i * 256];
    __syncthreads();
    const float4* w4 = (const float4*)(Wc + (size_t)c * (2 * NH));
    const float4* c4 = (const float4*)cs;
    float acc = 0.f;
#pragma unroll
    for (int i = 0; i < 32; i++) {
        int k = sub + i * 8;
        float4 w = w4[k], h = c4[k];
        acc += w.x * h.x + w.y * h.y + w.z * h.z + w.w * h.w;
    }
#pragma unroll
    for (int o = 4; o; o >>= 1) acc += __shfl_xor_sync(0xffffffffu, acc, o);
    if (sub == 0) g_projctx[b * NH + c] = acc + bc[c];
}

// ---------------- K10: logits, single fp16 x fp16 --------------
#define SXS 36
__global__ void __launch_bounds__(256) k_logits_mma(const float* __restrict__ Wo,
                                                    const float* __restrict__ bo,
                                                    float* __restrict__ out) {
    __shared__ __half sAh[64 * SXS];
    __shared__ __half sWh[128 * SXS];
    int t = threadIdx.x;
    int col0 = blockIdx.x * 128;
    int wid = t >> 5, lane = t & 31;
    int wm = wid >> 2, wn = wid & 3;
    int g = lane >> 2, tig = lane & 3;

    float acc[2][4][4] = {};

    for (int k0 = 0; k0 < 512; k0 += 32) {
        __syncthreads();
#pragma unroll
        for (int i = 0; i < 2; i++) {
            int idx = t + i * 256;
            int r = idx >> 3, fc = idx & 7;
            float4 v = *(const float4*)(g_fused + (size_t)r * 512 + k0 + fc * 4);
            int sidx = r * SXS + fc * 4;
            sAh[sidx + 0] = __float2half(v.x);
            sAh[sidx + 1] = __float2half(v.y);
            sAh[sidx + 2] = __float2half(v.z);
            sAh[sidx + 3] = __float2half(v.w);
        }
#pragma unroll
        for (int i = 0; i < 4; i++) {
            int idx = t + i * 256;
            int r = idx >> 3, fc = idx & 7;
            float4 v = *(const float4*)(Wo + (size_t)(col0 + r) * 512 + k0 + fc * 4);
            int sidx = r * SXS + fc * 4;
            sWh[sidx + 0] = __float2half(v.x);
            sWh[sidx + 1] = __float2half(v.y);
            sWh[sidx + 2] = __float2half(v.z);
            sWh[sidx + 3] = __float2half(v.w);
        }
        __syncthreads();
#pragma unroll
        for (int kk = 0; kk < 32; kk += 16) {
            unsigned ah[2][4], bh[4][2];
#pragma unroll
            for (int mt = 0; mt < 2; mt++) {
                int rb = wm * 32 + mt * 16;
                int b0 = (rb + g) * SXS + kk + tig * 2;
                int b1 = (rb + g + 8) * SXS + kk + tig * 2;
                ah[mt][0] = *(const unsigned*)&sAh[b0];
                ah[mt][1] = *(const unsigned*)&sAh[b1];
                ah[mt][2] = *(const unsigned*)&sAh[b0 + 8];
                ah[mt][3] = *(const unsigned*)&sAh[b1 + 8];
            }
#pragma unroll
            for (int nt = 0; nt < 4; nt++) {
                int nb = (wn * 32 + nt * 8 + g) * SXS + kk + tig * 2;
                bh[nt][0] = *(const unsigned*)&sWh[nb];
                bh[nt][1] = *(const unsigned*)&sWh[nb + 8];
            }
#pragma unroll
            for (int mt = 0; mt < 2; mt++)
#pragma unroll
                for (int nt = 0; nt < 4; nt++) {
                    mma_fp16(acc[mt][nt], ah[mt], bh[nt]);
                }
        }
    }
#pragma unroll
    for (int mt = 0; mt < 2; mt++) {
        int r = wm * 32 + mt * 16 + g;
#pragma unroll
        for (int nt = 0; nt < 4; nt++) {
            int c = col0 + wn * 32 + nt * 8 + tig * 2;
            out[(size_t)r * NV + c]           = acc[mt][nt][0] + bo[c];
            out[(size_t)r * NV + c + 1]       = acc[mt][nt][1] + bo[c + 1];
            out[(size_t)(r + 8) * NV + c]     = acc[mt][nt][2] + bo[c];
            out[(size_t)(r + 8) * NV + c + 1] = acc[mt][nt][3] + bo[c + 1];
        }
    }
}

// ---------------- launch ----------------
extern "C" void kernel_launch(void* const* d_in, const int* in_sizes, int n_in,
                              void* d_out, int out_size) {
    const int*   tok   = (const int*)d_in[0];
    const float* h0    = (const float*)d_in[1];
    const float* c0    = (const float*)d_in[2];
    const float* enc   = (const float*)d_in[3];
    const int*   mask  = (const int*)d_in[4];
    const float* emb   = (const float*)d_in[5];
    const float* lng   = (const float*)d_in[6];
    const float* lnb   = (const float*)d_in[7];
    const float* W_enc = (const float*)d_in[8];
    const float* b_enc = (const float*)d_in[9];
    const float* W_dec = (const float*)d_in[10];
    const float* b_dec = (const float*)d_in[11];
    const float* v_att = (const float*)d_in[12];
    const float* lag   = (const float*)d_in[13];
    const float* lab   = (const float*)d_in[14];
    const float* W_ih0 = (const float*)d_in[15];
    const float* W_hh0 = (const float*)d_in[16];
    const float* b_ih0 = (const float*)d_in[17];
    const float* b_hh0 = (const float*)d_in[18];
    const float* W_ih1 = (const float*)d_in[19];
    const float* W_hh1 = (const float*)d_in[20];
    const float* b_ih1 = (const float*)d_in[21];
    const float* b_hh1 = (const float*)d_in[22];
    const float* llg   = (const float*)d_in[23];
    const float* llb   = (const float*)d_in[24];
    const float* W_ctx = (const float*)d_in[25];
    const float* b_ctx = (const float*)d_in[26];
    const float* W_out = (const float*)d_in[27];
    const float* b_out = (const float*)d_in[28];

    float* out = (float*)d_out;
    float* out_logits = out;
    float* out_h = out + (size_t)NB * NV;
    float* out_c = out_h + 2 * NB * NH;
    float* out_attn = out_c + 2 * NB * NH;

    cudaFuncSetAttribute(k_attn_mma2, cudaFuncAttributeMaxDynamicSharedMemorySize, 48 * 1024);

    int encN4 = NB * NS * 1024 / 4;           // 4,194,304 float4s
    int half4 = encN4 / 2;
    // launches 1-5 precede attn so ncu (-s 5 -c 1) samples k_attn_mma2 as launch #6
    k_tohalf<0><<<(half4 + 255) / 256, 256>>>(enc, 0, half4);
    k_tohalf<0><<<(half4 + 255) / 256, 256>>>(enc, half4, half4);
    k_tohalf<1><<<(NA * 1024 / 4 + 255) / 256, 256>>>(W_enc, 0, NA * 1024 / 4);
    k_embed_ln<<<NB, 512>>>(tok, emb, lng, lnb);
    k_dec_proj<<<dim3(NB, 16), 256>>>(h0, W_dec, b_dec);
    k_attn_mma2<<<dim3(4, 128), 256, 40960>>>();
    k_copy_h0<<<NB, 512>>>(h0);
    k_attn_epi<<<2048, 256>>>(b_enc, v_att, lag, lab);
    k_ctx<<<dim3(NB, 8), 256>>>(mask, enc, out_attn);
    k_projctx<<<dim3(NB, 16), 256>>>(W_ctx, b_ctx);
    k_gates<2048, 1536, 0><<<dim3(128, 4), 256>>>(W_ih0, W_hh0);
    k_cell0<<<NB, 512>>>(c0, out_h, out_c, b_ih0, b_hh0);
    k_gates<1024, 512, 1><<<dim3(128, 4), 256>>>(W_ih1, W_hh1);
    k_cell1<<<NB, 512>>>(c0 + (size_t)NB * NH, out_h + (size_t)NB * NH, out_c + (size_t)NB * NH,
                         b_ih1, b_hh1, llg, llb);
    k_logits_mma<<<NV / 128, 256>>>(W_out, b_out, out_logits);
}

// round 17
// speedup vs baseline: 1.4592x; 1.0133x over previous
#include <cuda_runtime.h>
#include <cuda_bf16.h>
#include <cuda_fp16.h>
#include <math.h>

#define NB 64
#define NS 256
#define NV 32000
#define NE 512
#define NH 512
#define NA 512
#define EPSV 1e-5f

// ---------------- scratch (__device__ globals; no allocations allowed) ----------------
__device__ float g_dec_proj[NB * NA];
__device__ float g_scores[NB * NS];
__device__ float g_u0[NB * 2048];                    // [emb(512) | ctx(1024) | h0[0](512)]
__device__ float g_u1[NB * 1024];                    // [h_l0(512) | h0[1](512)]
__device__ float g_gates_part[4][NB * 2048];
__device__ float g_projctx[NB * NH];
__device__ float g_fused[NB * NH];
__device__ __half g_combH[(size_t)NB * NS * NA];     // 16384 x 512 enc_proj scratch (fp16)
__device__ __half g_encH[(size_t)NB * NS * 1024];    // enc fp16
__device__ __half g_WeH[NA * 1024];                  // W_enc fp16

// ---------------- helpers ----------------
__device__ __forceinline__ float blk_sum(float v, float* red) {
    int t = threadIdx.x, lane = t & 31, w = t >> 5, nw = blockDim.x >> 5;
#pragma unroll
    for (int o = 16; o; o >>= 1) v += __shfl_xor_sync(0xffffffffu, v, o);
    if (lane == 0) red[w] = v;
    __syncthreads();
    if (w == 0) {
        float x = (lane < nw) ? red[lane] : 0.f;
#pragma unroll
        for (int o = 16; o; o >>= 1) x += __shfl_xor_sync(0xffffffffu, x, o);
        if (lane == 0) red[0] = x;
    }
    __syncthreads();
    float r = red[0];
    __syncthreads();
    return r;
}

__device__ __forceinline__ float blk_max(float v, float* red) {
    int t = threadIdx.x, lane = t & 31, w = t >> 5, nw = blockDim.x >> 5;
#pragma unroll
    for (int o = 16; o; o >>= 1) v = fmaxf(v, __shfl_xor_sync(0xffffffffu, v, o));
    if (lane == 0) red[w] = v;
    __syncthreads();
    if (w == 0) {
        float x = (lane < nw) ? red[lane] : -INFINITY;
#pragma unroll
        for (int o = 16; o; o >>= 1) x = fmaxf(x, __shfl_xor_sync(0xffffffffu, x, o));
        if (lane == 0) red[0] = x;
    }
    __syncthreads();
    float r = red[0];
    __syncthreads();
    return r;
}

__device__ __forceinline__ float sigm(float x) { return 1.f / (1.f + expf(-x)); }

__device__ __forceinline__ void mma_fp16(float* d, const unsigned* a, const unsigned* b) {
    asm volatile(
        "mma.sync.aligned.m16n8k16.row.col.f32.f16.f16.f32 "
        "{%0,%1,%2,%3},{%4,%5,%6,%7},{%8,%9},{%0,%1,%2,%3};\n"
        : "+f"(d[0]), "+f"(d[1]), "+f"(d[2]), "+f"(d[3])
        : "r"(a[0]), "r"(a[1]), "r"(a[2]), "r"(a[3]), "r"(b[0]), "r"(b[1]));
}

__device__ __forceinline__ void ldsm4(unsigned* r, unsigned addr) {
    asm volatile("ldmatrix.sync.aligned.m8n8.x4.shared.b16 {%0,%1,%2,%3}, [%4];"
                 : "=r"(r[0]), "=r"(r[1]), "=r"(r[2]), "=r"(r[3]) : "r"(addr));
}

__device__ __forceinline__ void cpasync16(unsigned dst, const void* src) {
    asm volatile("cp.async.cg.shared.global [%0], [%1], 16;" :: "r"(dst), "l"(src));
}

// ---------------- K0: fp32 -> fp16 convert (range of float4s) ----------------
template <int DST>   // 0: enc -> g_encH ; 1: W_enc -> g_WeH
__global__ void k_tohalf(const float* __restrict__ src, int base4, int n4) {
    int i = blockIdx.x * 256 + threadIdx.x;
    if (i >= n4) return;
    i += base4;
    float4 v = ((const float4*)src)[i];
    __half2* hp = (DST == 0) ? (__half2*)g_encH : (__half2*)g_WeH;
    __half2 H0; H0.x = __float2half(v.x); H0.y = __float2half(v.y);
    __half2 H1; H1.x = __float2half(v.z); H1.y = __float2half(v.w);
    hp[i * 2] = H0; hp[i * 2 + 1] = H1;
}

// ---------------- K1: embedding gather + LN -> g_u0[:,0:512]; also copy h0 slices ---------
__global__ void k_embed_ln(const int* __restrict__ tok, const float* __restrict__ emb,
                           const float* __restrict__ lg, const float* __restrict__ lb,
                           const float* __restrict__ h0) {
    __shared__ float red[32];
    int b = blockIdx.x, t = threadIdx.x;
    int token = tok[b];
    float x = emb[(size_t)token * NE + t];
    // fold former k_copy_h0: static slices of u0/u1
    g_u0[b * 2048 + 1536 + t] = h0[(size_t)b * NH + t];          // h0[0]
    g_u1[b * 1024 + 512 + t] = h0[(size_t)(NB + b) * NH + t];    // h0[1]
    float mean = blk_sum(x, red) * (1.f / NE);
    float d = x - mean;
    float var = blk_sum(d * d, red) * (1.f / NE);
    float rstd = rsqrtf(var + EPSV);
    g_u0[b * 2048 + t] = d * rstd * lg[t] + lb[t];
}

// ---------------- K2: dec_proj, 8-thread split-K. grid (64,16), block 256 ----------------
__global__ void k_dec_proj(const float* __restrict__ h0, const float* __restrict__ Wd,
                           const float* __restrict__ bd) {
    __shared__ float hs[NH];
    int b = blockIdx.x, t = threadIdx.x;
    int gid = t >> 3, sub = t & 7;
    int c = blockIdx.y * 32 + gid;
    hs[t] = h0[(size_t)(NB + b) * NH + t];
    hs[t + 256] = h0[(size_t)(NB + b) * NH + t + 256];
    __syncthreads();
    const float4* w4 = (const float4*)(Wd + (size_t)c * NH);
    const float4* h4 = (const float4*)hs;
    float acc = 0.f;
#pragma unroll
    for (int i = 0; i < 16; i++) {
        int k = sub + i * 8;
        float4 w = w4[k], h = h4[k];
        acc += w.x * h.x + w.y * h.y + w.z * h.z + w.w * h.w;
    }
#pragma unroll
    for (int o = 4; o; o >>= 1) acc += __shfl_xor_sync(0xffffffffu, acc, o);
    if (sub == 0) g_dec_proj[b * NA + c] = acc + bd[c];
}

// ---------------- K3a: enc_proj GEMM, single fp16 x fp16, fp16 output, 2 CTAs/SM ----------
// C[16384,512] = enc[16384,1024] @ W_enc^T.  Block tile 128x128, KC=32, 256 thr (2x4 warps).
__global__ void __launch_bounds__(256, 2) k_attn_mma2() {
    extern __shared__ __half sm[];
    unsigned sbase = (unsigned)__cvta_generic_to_shared(sm);
    int t = threadIdx.x;
    int row0 = blockIdx.y * 128, col0 = blockIdx.x * 128;
    int wid = t >> 5, lane = t & 31;
    int wm = wid >> 2, wn = wid & 3;          // 2x4 warp grid, warp tile 64x32
    int g = lane >> 2, tig = lane & 3;
    int lrow = lane & 15, lcol = lane >> 4;

    float acc[4][4][4] = {};

    auto stage = [&](int buf, int k0) {
#pragma unroll
        for (int i = 0; i < 2; i++) {
            int c = t + i * 256;
            int r = c >> 2, c8 = (c & 3) * 8;
            size_t gA = (size_t)(row0 + r) * 1024 + k0 + c8;
            size_t gB = (size_t)(col0 + r) * 1024 + k0 + c8;
            unsigned d = sbase + 2u * (buf * 10240 + r * 40 + c8);
            cpasync16(d,            g_encH + gA);
            cpasync16(d + 2 * 5120, g_WeH + gB);
        }
        asm volatile("cp.async.commit_group;" ::: "memory");
    };

    stage(0, 0);
    int buf = 0;
    for (int ki = 0; ki < 32; ki++) {
        if (ki < 31) {
            stage(buf ^ 1, (ki + 1) * 32);
            asm volatile("cp.async.wait_group 1;" ::: "memory");
        } else {
            asm volatile("cp.async.wait_group 0;" ::: "memory");
        }
        __syncthreads();
        int base = buf * 10240;
#pragma unroll
        for (int kk = 0; kk < 32; kk += 16) {
            unsigned ah[4][4], bh[2][4];
#pragma unroll
            for (int mt = 0; mt < 4; mt++) {
                unsigned ad = sbase + 2u * (base + (wm * 64 + mt * 16 + lrow) * 40 + kk + lcol * 8);
                ldsm4(ah[mt], ad);
            }
#pragma unroll
            for (int p = 0; p < 2; p++) {
                unsigned bd = sbase + 2u * (base + 5120 + (wn * 32 + p * 16 + lrow) * 40 + kk + lcol * 8);
                ldsm4(bh[p], bd);
            }
#pragma unroll
            for (int mt = 0; mt < 4; mt++)
#pragma unroll
                for (int nt = 0; nt < 4; nt++) {
                    int p = nt >> 1, h = nt & 1;
                    unsigned bhf[2] = {bh[p][h], bh[p][h + 2]};
                    mma_fp16(acc[mt][nt], ah[mt], bhf);
                }
        }
        __syncthreads();
        buf ^= 1;
    }
#pragma unroll
    for (int mt = 0; mt < 4; mt++) {
        int r = row0 + wm * 64 + mt * 16 + g;
#pragma unroll
        for (int nt = 0; nt < 4; nt++) {
            int c = col0 + wn * 32 + nt * 8 + tig * 2;
            *(__half2*)&g_combH[(size_t)r * NA + c] =
                __floats2half2_rn(acc[mt][nt][0], acc[mt][nt][1]);
            *(__half2*)&g_combH[(size_t)(r + 8) * NA + c] =
                __floats2half2_rn(acc[mt][nt][2], acc[mt][nt][3]);
        }
    }
}

// ---------------- K3b: epilogue (+smem-cached dec_proj+b_enc), LN, tanh, dot(v) ------------
__global__ void __launch_bounds__(256) k_attn_epi(const float* __restrict__ be,
                                                  const float* __restrict__ va,
                                                  const float* __restrict__ lg,
                                                  const float* __restrict__ lb) {
    __shared__ float s_d[512];
    int t = threadIdx.x;
    int wid = t >> 5, lane = t & 31;
    int row = blockIdx.x * 8 + wid;     // row = b*256 + s
    int b = blockIdx.x >> 5;            // 32 blocks per batch element
    s_d[t] = g_dec_proj[b * NA + t] + be[t];
    s_d[t + 256] = g_dec_proj[b * NA + t + 256] + be[t + 256];
    __syncthreads();
    const __half* src = g_combH + (size_t)row * NA;
    float x[16];
#pragma unroll
    for (int i = 0; i < 16; i++) {
        int c = lane + i * 32;
        x[i] = __half2float(src[c]) + s_d[c];
    }
    float s = 0.f;
#pragma unroll
    for (int i = 0; i < 16; i++) s += x[i];
#pragma unroll
    for (int o = 16; o; o >>= 1) s += __shfl_xor_sync(0xffffffffu, s, o);
    float mean = s * (1.f / 512.f);
    float vs = 0.f;
#pragma unroll
    for (int i = 0; i < 16; i++) { float d = x[i] - mean; vs += d * d; }
#pragma unroll
    for (int o = 16; o; o >>= 1) vs += __shfl_xor_sync(0xffffffffu, vs, o);
    float rstd = rsqrtf(vs * (1.f / 512.f) + EPSV);
    float sc = 0.f;
#pragma unroll
    for (int i = 0; i < 16; i++) {
        int c = lane + i * 32;
        sc += tanhf((x[i] - mean) * rstd * lg[c] + lb[c]) * va[c];
    }
#pragma unroll
    for (int o = 16; o; o >>= 1) sc += __shfl_xor_sync(0xffffffffu, sc, o);
    if (lane == 0) g_scores[row] = sc;
}

// ---------------- K4: fused softmax + context -> g_u0[:, 512:1536]. grid (64,8) ----------
__global__ void __launch_bounds__(256) k_ctx(const int* __restrict__ mask,
                                             const float* __restrict__ enc,
                                             float* __restrict__ out_attn) {
    __shared__ float red[32];
    __shared__ float ws[NS];
    __shared__ float4 part[256];
    int b = blockIdx.x, q = blockIdx.y, t = threadIdx.x;
    float sc = g_scores[b * NS + t];
    if (mask[b * NS + t] == 0) sc = -INFINITY;
    float mx = blk_max(sc, red);
    float e = expf(sc - mx);
    float sum = blk_sum(e, red);
    float wv = e / sum;
    ws[t] = wv;
    if (q == 0) out_attn[b * NS + t] = wv;
    __syncthreads();
    int cc = t & 31, sg = t >> 5;
    int f4 = q * 32 + cc;
    const float4* ep = (const float4*)(enc + (size_t)b * NS * 1024);
    float4 acc = make_float4(0.f, 0.f, 0.f, 0.f);
#pragma unroll 4
    for (int s = sg; s < NS; s += 8) {
        float w = ws[s];
        float4 ev = ep[s * 256 + f4];
        acc.x += w * ev.x; acc.y += w * ev.y; acc.z += w * ev.z; acc.w += w * ev.w;
    }
    part[t] = acc;
    __syncthreads();
    if (t < 32) {
        float4 r = part[t];
#pragma unroll
        for (int g2 = 1; g2 < 8; g2++) {
            float4 p = part[g2 * 32 + t];
            r.x += p.x; r.y += p.y; r.z += p.z; r.w += p.w;
        }
        *(float4*)&g_u0[b * 2048 + 512 + (q * 32 + t) * 4] = r;
    }
}

// ---------------- K6: LSTM gate GEMM, split-K x4 into partials. grid (128,4) -------------
template <int K, int KX, int UID>
__global__ void __launch_bounds__(256) k_gates(const float* __restrict__ Wih,
                                               const float* __restrict__ Whh) {
    constexpr int KH = K - KX;
    constexpr int KQ = K / 4;
    const float* U = (UID == 0) ? g_u0 : g_u1;
    __shared__ float Us[64 * 16];
    __shared__ float Wt[16 * 20];
    int t = threadIdx.x;
    int colBase = blockIdx.x * 16;
    int kchunk = blockIdx.y;
    int r = t >> 2;
    int tc = t & 3;
    float acc[4] = {0.f, 0.f, 0.f, 0.f};

    for (int k0 = kchunk * KQ; k0 < (kchunk + 1) * KQ; k0 += 16) {
        __syncthreads();
        {
            float4 v = *(const float4*)(U + (size_t)r * K + k0 + tc * 4);
            *(float4*)&Us[r * 16 + tc * 4] = v;
        }
        if (t < 64) {
            int c = r;
            int col = colBase + c;
            const float* src = (k0 < KX) ? (Wih + (size_t)col * KX + k0)
                                         : (Whh + (size_t)col * KH + (k0 - KX));
            float4 v = *(const float4*)(src + tc * 4);
            *(float4*)&Wt[c * 20 + tc * 4] = v;
        }
        __syncthreads();
#pragma unroll
        for (int kq = 0; kq < 4; kq++) {
            float4 x = *(const float4*)&Us[r * 16 + kq * 4];
#pragma unroll
            for (int j = 0; j < 4; j++) {
                int c = tc + 4 * j;
                float4 wv = *(const float4*)&Wt[c * 20 + kq * 4];
                acc[j] += x.x * wv.x + x.y * wv.y + x.z * wv.z + x.w * wv.w;
            }
        }
    }
#pragma unroll
    for (int j = 0; j < 4; j++) {
        int c = colBase + tc + 4 * j;
        g_gates_part[kchunk][(size_t)r * (4 * NH) + c] = acc[j];
    }
}

// ---------------- gate partial summation helper ----------------
__device__ __forceinline__ void gate_sums(int b, int j, const float* bih, const float* bhh,
                                          float& gi, float& gf, float& gg, float& go) {
    size_t base = (size_t)b * 2048;
    gi = gf = gg = go = 0.f;
#pragma unroll
    for (int p = 0; p < 4; p++) {
        gi += g_gates_part[p][base + j];
        gf += g_gates_part[p][base + j + 512];
        gg += g_gates_part[p][base + j + 1024];
        go += g_gates_part[p][base + j + 1536];
    }
    gi += bih[j] + bhh[j];
    gf += bih[j + 512] + bhh[j + 512];
    gg += bih[j + 1024] + bhh[j + 1024];
    go += bih[j + 1536] + bhh[j + 1536];
}

// ---------------- K7a: LSTM cell layer 0 (h -> g_u1 lower half) ----------------
__global__ void k_cell0(const float* __restrict__ cprev, float* __restrict__ hOut,
                        float* __restrict__ cOut, const float* __restrict__ bih,
                        const float* __restrict__ bhh) {
    int b = blockIdx.x, j = threadIdx.x;
    float gi, gf, gg, go;
    gate_sums(b, j, bih, bhh, gi, gf, gg, go);
    float ig = sigm(gi), fg = sigm(gf), gt = tanhf(gg), og = sigm(go);
    float c = fg * cprev[(size_t)b * NH + j] + ig * gt;
    float h = og * tanhf(c);
    g_u1[b * 1024 + j] = h;
    hOut[b * NH + j] = h;
    cOut[b * NH + j] = c;
}

// ---------------- K7b: LSTM cell layer 1 + fused LN + projctx -> g_fused ----------------
__global__ void k_cell1(const float* __restrict__ cprev, float* __restrict__ hOut,
                        float* __restrict__ cOut, const float* __restrict__ bih,
                        const float* __restrict__ bhh, const float* __restrict__ lg,
                        const float* __restrict__ lb) {
    __shared__ float red[32];
    int b = blockIdx.x, j = threadIdx.x;
    float gi, gf, gg, go;
    gate_sums(b, j, bih, bhh, gi, gf, gg, go);
    float ig = sigm(gi), fg = sigm(gf), gt = tanhf(gg), og = sigm(go);
    float c = fg * cprev[(size_t)b * NH + j] + ig * gt;
    float h = og * tanhf(c);
    hOut[b * NH + j] = h;
    cOut[b * NH + j] = c;
    float mean = blk_sum(h, red) * (1.f / NH);
    float d = h - mean;
    float var = blk_sum(d * d, red) * (1.f / NH);
    float rstd = rsqrtf(var + EPSV);
    g_fused[b * NH + j] = d * rstd * lg[j] + lb[j] + g_projctx[b * NH + j];
}

// ---------------- K8: proj_ctx (ctx from g_u0), 8-thread split-K. grid (64,16) ------------
__global__ void k_projctx(const float* __restrict__ Wc, const float* __restrict__ bc) {
    __shared__ float cs[2 * NH];
    int b = blockIdx.x, t = threadIdx.x;
    int gid = t >> 3, sub = t & 7;
    int c = blockIdx.y * 32 + gid;
#pragma unroll
    for (int i = 0; i < 4; i++) cs[t + i * 256] = g_u0[b * 2048 + 512 + t + i * 256];
    __syncthreads();
    const float4* w4 = (const float4*)(Wc + (size_t)c * (2 * NH));
    const float4* c4 = (const float4*)cs;
    float acc = 0.f;
#pragma unroll
    for (int i = 0; i < 32; i++) {
        int k = sub + i * 8;
        float4 w = w4[k], h = c4[k];
        acc += w.x * h.x + w.y * h.y + w.z * h.z + w.w * h.w;
    }
#pragma unroll
    for (int o = 4; o; o >>= 1) acc += __shfl_xor_sync(0xffffffffu, acc, o);
    if (sub == 0) g_projctx[b * NH + c] = acc + bc[c];
}

// ---------------- K10: logits, single fp16 x fp16 --------------
#define SXS 36
__global__ void __launch_bounds__(256) k_logits_mma(const float* __restrict__ Wo,
                                                    const float* __restrict__ bo,
                                                    float* __restrict__ out) {
    __shared__ __half sAh[64 * SXS];
    __shared__ __half sWh[128 * SXS];
    int t = threadIdx.x;
    int col0 = blockIdx.x * 128;
    int wid = t >> 5, lane = t & 31;
    int wm = wid >> 2, wn = wid & 3;
    int g = lane >> 2, tig = lane & 3;

    float acc[2][4][4] = {};

    for (int k0 = 0; k0 < 512; k0 += 32) {
        __syncthreads();
#pragma unroll
        for (int i = 0; i < 2; i++) {
            int idx = t + i * 256;
            int r = idx >> 3, fc = idx & 7;
            float4 v = *(const float4*)(g_fused + (size_t)r * 512 + k0 + fc * 4);
            int sidx = r * SXS + fc * 4;
            sAh[sidx + 0] = __float2half(v.x);
            sAh[sidx + 1] = __float2half(v.y);
            sAh[sidx + 2] = __float2half(v.z);
            sAh[sidx + 3] = __float2half(v.w);
        }
#pragma unroll
        for (int i = 0; i < 4; i++) {
            int idx = t + i * 256;
            int r = idx >> 3, fc = idx & 7;
            float4 v = *(const float4*)(Wo + (size_t)(col0 + r) * 512 + k0 + fc * 4);
            int sidx = r * SXS + fc * 4;
            sWh[sidx + 0] = __float2half(v.x);
            sWh[sidx + 1] = __float2half(v.y);
            sWh[sidx + 2] = __float2half(v.z);
            sWh[sidx + 3] = __float2half(v.w);
        }
        __syncthreads();
#pragma unroll
        for (int kk = 0; kk < 32; kk += 16) {
            unsigned ah[2][4], bh[4][2];
#pragma unroll
            for (int mt = 0; mt < 2; mt++) {
                int rb = wm * 32 + mt * 16;
                int b0 = (rb + g) * SXS + kk + tig * 2;
                int b1 = (rb + g + 8) * SXS + kk + tig * 2;
                ah[mt][0] = *(const unsigned*)&sAh[b0];
                ah[mt][1] = *(const unsigned*)&sAh[b1];
                ah[mt][2] = *(const unsigned*)&sAh[b0 + 8];
                ah[mt][3] = *(const unsigned*)&sAh[b1 + 8];
            }
#pragma unroll
            for (int nt = 0; nt < 4; nt++) {
                int nb = (wn * 32 + nt * 8 + g) * SXS + kk + tig * 2;
                bh[nt][0] = *(const unsigned*)&sWh[nb];
                bh[nt][1] = *(const unsigned*)&sWh[nb + 8];
            }
#pragma unroll
            for (int mt = 0; mt < 2; mt++)
#pragma unroll
                for (int nt = 0; nt < 4; nt++) {
                    mma_fp16(acc[mt][nt], ah[mt], bh[nt]);
                }
        }
    }
#pragma unroll
    for (int mt = 0; mt < 2; mt++) {
        int r = wm * 32 + mt * 16 + g;
#pragma unroll
        for (int nt = 0; nt < 4; nt++) {
            int c = col0 + wn * 32 + nt * 8 + tig * 2;
            out[(size_t)r * NV + c]           = acc[mt][nt][0] + bo[c];
            out[(size_t)r * NV + c + 1]       = acc[mt][nt][1] + bo[c + 1];
            out[(size_t)(r + 8) * NV + c]     = acc[mt][nt][2] + bo[c];
            out[(size_t)(r + 8) * NV + c + 1] = acc[mt][nt][3] + bo[c + 1];
        }
    }
}

// ---------------- launch ----------------
extern "C" void kernel_launch(void* const* d_in, const int* in_sizes, int n_in,
                              void* d_out, int out_size) {
    const int*   tok   = (const int*)d_in[0];
    const float* h0    = (const float*)d_in[1];
    const float* c0    = (const float*)d_in[2];
    const float* enc   = (const float*)d_in[3];
    const int*   mask  = (const int*)d_in[4];
    const float* emb   = (const float*)d_in[5];
    const float* lng   = (const float*)d_in[6];
    const float* lnb   = (const float*)d_in[7];
    const float* W_enc = (const float*)d_in[8];
    const float* b_enc = (const float*)d_in[9];
    const float* W_dec = (const float*)d_in[10];
    const float* b_dec = (const float*)d_in[11];
    const float* v_att = (const float*)d_in[12];
    const float* lag   = (const float*)d_in[13];
    const float* lab   = (const float*)d_in[14];
    const float* W_ih0 = (const float*)d_in[15];
    const float* W_hh0 = (const float*)d_in[16];
    const float* b_ih0 = (const float*)d_in[17];
    const float* b_hh0 = (const float*)d_in[18];
    const float* W_ih1 = (const float*)d_in[19];
    const float* W_hh1 = (const float*)d_in[20];
    const float* b_ih1 = (const float*)d_in[21];
    const float* b_hh1 = (const float*)d_in[22];
    const float* llg   = (const float*)d_in[23];
    const float* llb   = (const float*)d_in[24];
    const float* W_ctx = (const float*)d_in[25];
    const float* b_ctx = (const float*)d_in[26];
    const float* W_out = (const float*)d_in[27];
    const float* b_out = (const float*)d_in[28];

    float* out = (float*)d_out;
    float* out_logits = out;
    float* out_h = out + (size_t)NB * NV;
    float* out_c = out_h + 2 * NB * NH;
    float* out_attn = out_c + 2 * NB * NH;

    cudaFuncSetAttribute(k_attn_mma2, cudaFuncAttributeMaxDynamicSharedMemorySize, 48 * 1024);

    int encN4 = NB * NS * 1024 / 4;           // 4,194,304 float4s
    int half4 = encN4 / 2;
    // launches 1-5 precede attn so ncu (-s 5 -c 1) samples k_attn_mma2 as launch #6
    k_tohalf<0><<<(half4 + 255) / 256, 256>>>(enc, 0, half4);
    k_tohalf<0><<<(half4 + 255) / 256, 256>>>(enc, half4, half4);
    k_tohalf<1><<<(NA * 1024 / 4 + 255) / 256, 256>>>(W_enc, 0, NA * 1024 / 4);
    k_embed_ln<<<NB, 512>>>(tok, emb, lng, lnb, h0);
    k_dec_proj<<<dim3(NB, 16), 256>>>(h0, W_dec, b_dec);
    k_attn_mma2<<<dim3(4, 128), 256, 40960>>>();
    k_attn_epi<<<2048, 256>>>(b_enc, v_att, lag, lab);
    k_ctx<<<dim3(NB, 8), 256>>>(mask, enc, out_attn);
    k_projctx<<<dim3(NB, 16), 256>>>(W_ctx, b_ctx);
    k_gates<2048, 1536, 0><<<dim3(128, 4), 256>>>(W_ih0, W_hh0);
    k_cell0<<<NB, 512>>>(c0, out_h, out_c, b_ih0, b_hh0);
    k_gates<1024, 512, 1><<<dim3(128, 4), 256>>>(W_ih1, W_hh1);
    k_cell1<<<NB, 512>>>(c0 + (size_t)NB * NH, out_h + (size_t)NB * NH, out_c + (size_t)NB * NH,
                         b_ih1, b_hh1, llg, llb);
    k_logits_mma<<<NV / 128, 256>>>(W_out, b_out, out_logits);
}